// round 7
// baseline (speedup 1.0000x reference)
#include <cuda_runtime.h>
#include <cuda_bf16.h>

// ---------------- constants ----------------
#define HH 96
#define WW 96
#define NPIX 9216
#define BB 8

typedef unsigned int u32;
typedef unsigned long long ull;

// ---------------- scratch ----------------
__device__ float g_xt[BB * NPIX * 64];            // x channels-last f32
__device__ unsigned short g_wbhi[9 * 64 * 64];    // main-conv B bf16 hi, swizzled [n][oc][ch]
__device__ unsigned short g_wblo[9 * 64 * 64];
__device__ unsigned short g_wobhi[9 * 32 * 64];   // offset-conv B (24 rows used, padded 32)
__device__ unsigned short g_woblo[9 * 32 * 64];

// ---------------- helpers ----------------
__device__ __forceinline__ u32 s2u(const void* p) {
    u32 a; asm("{ .reg .u64 t; cvta.to.shared.u64 t, %1; cvt.u32.u64 %0, t; }" : "=r"(a) : "l"(p));
    return a;
}
__device__ __forceinline__ u32 swz(u32 b) { return b ^ ((b >> 3) & 0x70); }

__device__ __forceinline__ void ldsm4(u32 a, u32& r0, u32& r1, u32& r2, u32& r3) {
    asm volatile("ldmatrix.sync.aligned.m8n8.x4.shared.b16 {%0,%1,%2,%3}, [%4];"
                 : "=r"(r0), "=r"(r1), "=r"(r2), "=r"(r3) : "r"(a));
}
__device__ __forceinline__ void mma_bf16(float& d0, float& d1, float& d2, float& d3,
                                         u32 a0, u32 a1, u32 a2, u32 a3, u32 b0, u32 b1) {
    asm volatile("mma.sync.aligned.m16n8k16.row.col.f32.bf16.bf16.f32 "
                 "{%0,%1,%2,%3},{%4,%5,%6,%7},{%8,%9},{%0,%1,%2,%3};"
                 : "+f"(d0), "+f"(d1), "+f"(d2), "+f"(d3)
                 : "r"(a0), "r"(a1), "r"(a2), "r"(a3), "r"(b0), "r"(b1));
}
__device__ __forceinline__ void sts128(u32 a, u32 x, u32 y, u32 z, u32 w) {
    asm volatile("st.shared.v4.b32 [%0],{%1,%2,%3,%4};" :: "r"(a), "r"(x), "r"(y), "r"(z), "r"(w) : "memory");
}
__device__ __forceinline__ u32 bfhi2(float a, float b) {
    return __byte_perm(__float_as_uint(a), __float_as_uint(b), 0x7632);
}
__device__ __forceinline__ u32 bflo2(float a, float b) {
    float la = a - __uint_as_float(__float_as_uint(a) & 0xFFFF0000u);
    float lb = b - __uint_as_float(__float_as_uint(b) & 0xFFFF0000u);
    u32 r; asm("cvt.rn.bf16x2.f32 %0, %1, %2;" : "=r"(r) : "f"(lb), "f"(la));
    return r;
}
__device__ __forceinline__ ull pack2(float lo, float hi) {
    ull r; asm("mov.b64 %0, {%1,%2};" : "=l"(r) : "f"(lo), "f"(hi)); return r;
}
__device__ __forceinline__ void unpack2(ull v, float& lo, float& hi) {
    asm("mov.b64 {%0,%1}, %2;" : "=f"(lo), "=f"(hi) : "l"(v));
}
__device__ __forceinline__ ull mul2(ull a, ull b) {
    ull r; asm("mul.rn.f32x2 %0, %1, %2;" : "=l"(r) : "l"(a), "l"(b)); return r;
}
__device__ __forceinline__ void fma2(ull& d, ull a, ull b) {
    asm("fma.rn.f32x2 %0, %1, %2, %0;" : "+l"(d) : "l"(a), "l"(b));
}

// ================= K1: transpose x (b,c,h,w) -> (b,hw,c) =================
__global__ __launch_bounds__(256) void k_transpose(const float* __restrict__ x) {
    __shared__ float tile[64][65];
    int b  = blockIdx.y;
    int p0 = blockIdx.x << 6;
    int t  = threadIdx.x;
    #pragma unroll
    for (int i = t; i < 4096; i += 256) {
        int c = i >> 6, p = i & 63;
        tile[c][p] = x[((size_t)(b * 64 + c)) * NPIX + p0 + p];
    }
    __syncthreads();
    #pragma unroll
    for (int i = t; i < 4096; i += 256) {
        int p = i >> 6, c = i & 63;
        g_xt[((size_t)b * NPIX + p0 + p) * 64 + c] = tile[c][p];
    }
}

// ================= K0: weight prep =================
__global__ __launch_bounds__(256) void k_prep(const float* __restrict__ wker,
                                              const float* __restrict__ wof) {
    int i = blockIdx.x * 256 + threadIdx.x;
    if (i < 9 * 4096) {
        int n = i >> 12, r = i & 4095, oc = r >> 6, ch = r & 63;
        float v = wker[(oc * 64 + ch) * 9 + n];
        u32 hib = __float_as_uint(v) & 0xFFFF0000u;
        float lv = v - __uint_as_float(hib);
        __nv_bfloat16 lb = __float2bfloat16(lv);
        u32 sw = swz((u32)(oc * 128 + ch * 2)) >> 1;
        g_wbhi[n * 4096 + sw] = (unsigned short)(hib >> 16);
        g_wblo[n * 4096 + sw] = *(unsigned short*)&lb;
    } else {
        int j = i - 9 * 4096;
        if (j < 9 * 2048) {
            int n = j >> 11, r = j & 2047, oc = r >> 6, ch = r & 63;
            float v = (oc < 18) ? wof[(oc * 64 + ch) * 9 + n] : 0.f;
            u32 hib = __float_as_uint(v) & 0xFFFF0000u;
            float lv = v - __uint_as_float(hib);
            __nv_bfloat16 lb = __float2bfloat16(lv);
            u32 sw = swz((u32)(oc * 128 + ch * 2)) >> 1;
            g_wobhi[n * 2048 + sw] = (unsigned short)(hib >> 16);
            g_woblo[n * 2048 + sw] = *(unsigned short*)&lb;
        }
    }
}

// ================= K_MAIN =================
// smem layout: A ring 2 x (16K hi + 16K lo), B ring 2 x (8K hi + 8K lo), meta
#define AHI(s)  ((s) * 32768)
#define ALO(s)  ((s) * 32768 + 16384)
#define BHI(s)  (65536 + (s) * 16384)
#define BLO(s)  (65536 + (s) * 16384 + 8192)
#define OFF_MO  98304
#define OFF_MW  116736
#define SMEM_MAIN 135168

// sample one pixel's 8-channel slice (lane l8) for point n into stage tiles
__device__ __forceinline__ void sample_pix(const float* __restrict__ xb,
                                           const int4* __restrict__ mo,
                                           const float4* __restrict__ mw,
                                           int lp, int n, int l8,
                                           u32 aHiB, u32 aLoB) {
    int mi = lp * 9 + n;
    int4   o4 = mo[mi];
    float4 w4 = mw[mi];
    const float* pA = xb + o4.x + l8 * 8;
    const float* pB = xb + o4.y + l8 * 8;
    const float* pC = xb + o4.z + l8 * 8;
    const float* pD = xb + o4.w + l8 * 8;
    float4 A0 = *(const float4*)pA, A1 = *(const float4*)(pA + 4);
    float4 B0 = *(const float4*)pB, B1 = *(const float4*)(pB + 4);
    float4 C0 = *(const float4*)pC, C1 = *(const float4*)(pC + 4);
    float4 D0 = *(const float4*)pD, D1 = *(const float4*)(pD + 4);
    ull W00 = pack2(w4.x, w4.x), W10 = pack2(w4.y, w4.y);
    ull W01 = pack2(w4.z, w4.z), W11 = pack2(w4.w, w4.w);
    ull r0 = mul2(pack2(A0.x, A0.y), W00);
    ull r1 = mul2(pack2(A0.z, A0.w), W00);
    ull r2 = mul2(pack2(A1.x, A1.y), W00);
    ull r3 = mul2(pack2(A1.z, A1.w), W00);
    fma2(r0, pack2(B0.x, B0.y), W10); fma2(r1, pack2(B0.z, B0.w), W10);
    fma2(r2, pack2(B1.x, B1.y), W10); fma2(r3, pack2(B1.z, B1.w), W10);
    fma2(r0, pack2(C0.x, C0.y), W01); fma2(r1, pack2(C0.z, C0.w), W01);
    fma2(r2, pack2(C1.x, C1.y), W01); fma2(r3, pack2(C1.z, C1.w), W01);
    fma2(r0, pack2(D0.x, D0.y), W11); fma2(r1, pack2(D0.z, D0.w), W11);
    fma2(r2, pack2(D1.x, D1.y), W11); fma2(r3, pack2(D1.z, D1.w), W11);
    float s0, s1, s2, s3, s4, s5, s6, s7;
    unpack2(r0, s0, s1); unpack2(r1, s2, s3);
    unpack2(r2, s4, s5); unpack2(r3, s6, s7);
    u32 sa = swz((u32)(lp * 128 + l8 * 16));
    sts128(aHiB + sa, bfhi2(s0, s1), bfhi2(s2, s3), bfhi2(s4, s5), bfhi2(s6, s7));
    sts128(aLoB + sa, bflo2(s0, s1), bflo2(s2, s3), bflo2(s4, s5), bflo2(s6, s7));
}

__global__ __launch_bounds__(256, 1) void k_main(const float* __restrict__ bof,
                                                 const float* __restrict__ bker,
                                                 float* __restrict__ out) {
    extern __shared__ char smc[];
    u32 sb = s2u(smc);
    int t = threadIdx.x, wid = t >> 5, ln = t & 31;
    int b = blockIdx.y;
    int p0 = blockIdx.x * 128;
    const float* xb = g_xt + (size_t)b * NPIX * 64;

    // ========== PHASE 0: offset conv (3-term hi/lo split), all 8 warps ==========
    float acc0[3][4];
    #pragma unroll
    for (int nt = 0; nt < 3; nt++)
        #pragma unroll
        for (int j = 0; j < 4; j++) acc0[nt][j] = 0.f;

    {
        int lp = t >> 1, q = t & 1;
        int pix = p0 + lp, hh = pix / 96, ww = pix - hh * 96;
        u32 aHiB = sb + AHI(0), aLoB = sb + ALO(0);

        for (int tap = 0; tap < 9; tap++) {
            __syncthreads();
            ((uint4*)(smc + BHI(0)))[t] = ((const uint4*)g_wobhi + tap * 256)[t];
            ((uint4*)(smc + BLO(0)))[t] = ((const uint4*)g_woblo + tap * 256)[t];
            // A-build (hi + lo residual) from f32 channels-last
            {
                int sh_ = hh + tap / 3 - 1, sw_ = ww + tap % 3 - 1;
                bool ok = ((unsigned)sh_ < 96u) & ((unsigned)sw_ < 96u);
                float4 v[8];
                if (ok) {
                    const float4* src = (const float4*)(xb + (size_t)(sh_ * 96 + sw_) * 64) + q * 8;
                    #pragma unroll
                    for (int j = 0; j < 8; j++) v[j] = src[j];
                } else {
                    #pragma unroll
                    for (int j = 0; j < 8; j++) v[j] = make_float4(0.f, 0.f, 0.f, 0.f);
                }
                u32 rowb = (u32)(lp * 128 + q * 64);
                #pragma unroll
                for (int j = 0; j < 4; j++) {
                    u32 sa = swz(rowb + j * 16);
                    sts128(aHiB + sa, bfhi2(v[2*j].x, v[2*j].y), bfhi2(v[2*j].z, v[2*j].w),
                                      bfhi2(v[2*j+1].x, v[2*j+1].y), bfhi2(v[2*j+1].z, v[2*j+1].w));
                    sts128(aLoB + sa, bflo2(v[2*j].x, v[2*j].y), bflo2(v[2*j].z, v[2*j].w),
                                      bflo2(v[2*j+1].x, v[2*j+1].y), bflo2(v[2*j+1].z, v[2*j+1].w));
                }
            }
            __syncthreads();
            {
                u32 arow = (u32)((wid * 16 + (ln & 15)) * 128 + ((ln >> 4) * 16));
                u32 brow = (u32)(((((ln >> 4) << 3) + (ln & 7))) * 128 + (((ln >> 3) & 1) * 16));
                u32 bHiB = sb + BHI(0), bLoB = sb + BLO(0);
                #pragma unroll
                for (int k = 0; k < 4; k++) {
                    u32 ka = (u32)(k * 32);
                    u32 ah[4], al[4], bh[8], bl[8];
                    ldsm4(aHiB + swz(arow + ka), ah[0], ah[1], ah[2], ah[3]);
                    ldsm4(aLoB + swz(arow + ka), al[0], al[1], al[2], al[3]);
                    ldsm4(bHiB + swz(brow + ka), bh[0], bh[1], bh[2], bh[3]);
                    ldsm4(bHiB + swz(brow + 2048 + ka), bh[4], bh[5], bh[6], bh[7]);
                    ldsm4(bLoB + swz(brow + ka), bl[0], bl[1], bl[2], bl[3]);
                    ldsm4(bLoB + swz(brow + 2048 + ka), bl[4], bl[5], bl[6], bl[7]);
                    #pragma unroll
                    for (int nt = 0; nt < 3; nt++) {
                        mma_bf16(acc0[nt][0], acc0[nt][1], acc0[nt][2], acc0[nt][3],
                                 ah[0], ah[1], ah[2], ah[3], bh[nt*2], bh[nt*2+1]);
                        mma_bf16(acc0[nt][0], acc0[nt][1], acc0[nt][2], acc0[nt][3],
                                 al[0], al[1], al[2], al[3], bh[nt*2], bh[nt*2+1]);
                        mma_bf16(acc0[nt][0], acc0[nt][1], acc0[nt][2], acc0[nt][3],
                                 ah[0], ah[1], ah[2], ah[3], bl[nt*2], bl[nt*2+1]);
                    }
                }
            }
        }
    }
    __syncthreads();
    {
        float* dst = (float*)(smc + AHI(0));
        int pr = wid * 16 + (ln >> 2);
        int pc = (ln & 3) * 2;
        #pragma unroll
        for (int nt = 0; nt < 3; nt++) {
            dst[pr * 24 + nt * 8 + pc]           = acc0[nt][0];
            dst[pr * 24 + nt * 8 + pc + 1]       = acc0[nt][1];
            dst[(pr + 8) * 24 + nt * 8 + pc]     = acc0[nt][2];
            dst[(pr + 8) * 24 + nt * 8 + pc + 1] = acc0[nt][3];
        }
    }
    __syncthreads();
    {
        const float* dsm = (const float*)(smc + AHI(0));
        int4*   mo = (int4*)(smc + OFF_MO);
        float4* mw = (float4*)(smc + OFF_MW);
        for (int i = t; i < 1152; i += 256) {
            int lp = i / 9, n = i - lp * 9;
            int pix = p0 + lp, hh = pix / 96, ww = pix - hh * 96;
            float ox = dsm[lp * 24 + n]     + __ldg(bof + n);
            float oy = dsm[lp * 24 + 9 + n] + __ldg(bof + 9 + n);
            float px = (float)(hh + n / 3 - 1) + ox;
            float py = (float)(ww + n % 3 - 1) + oy;
            px = fminf(fmaxf(px, -10000.f), 10000.f);
            py = fminf(fmaxf(py, -10000.f), 10000.f);
            float fx = floorf(px), fy = floorf(py);
            float lx = px - fx, ly = py - fy;
            int x0 = (int)fx, y0 = (int)fy, x1 = x0 + 1, y1 = y0 + 1;
            float w00 = (1.f - lx) * (1.f - ly);
            float w10 = lx * (1.f - ly);
            float w01 = (1.f - lx) * ly;
            float w11 = lx * ly;
            if ((unsigned)x0 >= 96u) { w00 = 0.f; w01 = 0.f; }
            if ((unsigned)x1 >= 96u) { w10 = 0.f; w11 = 0.f; }
            if ((unsigned)y0 >= 96u) { w00 = 0.f; w10 = 0.f; }
            if ((unsigned)y1 >= 96u) { w01 = 0.f; w11 = 0.f; }
            int cx0 = min(max(x0, 0), 95), cx1 = min(max(x1, 0), 95);
            int cy0 = min(max(y0, 0), 95), cy1 = min(max(y1, 0), 95);
            mo[i] = make_int4((cx0 * 96 + cy0) * 64, (cx1 * 96 + cy0) * 64,
                              (cx0 * 96 + cy1) * 64, (cx1 * 96 + cy1) * 64);
            mw[i] = make_float4(w00, w10, w01, w11);
        }
    }
    __syncthreads();

    // ========== PHASE 1: producer/consumer pipelined main conv ==========
    const int4*   mo = (const int4*)(smc + OFF_MO);
    const float4* mw = (const float4*)(smc + OFF_MW);
    int l8 = ln & 7, g4 = ln >> 3;

    // prologue: all 8 warps stage B(0) + sample(0) into stage 0
    {
        const uint4* sh = (const uint4*)g_wbhi;   // n = 0
        const uint4* sl = (const uint4*)g_wblo;
        ((uint4*)(smc + BHI(0)))[t]       = sh[t];
        ((uint4*)(smc + BHI(0)))[t + 256] = sh[t + 256];
        ((uint4*)(smc + BLO(0)))[t]       = sl[t];
        ((uint4*)(smc + BLO(0)))[t + 256] = sl[t + 256];
        #pragma unroll
        for (int i = 0; i < 4; i++) {
            int lp = wid * 16 + i * 4 + g4;
            sample_pix(xb, mo, mw, lp, 0, l8, sb + AHI(0), sb + ALO(0));
        }
    }
    __syncthreads();

    float acc[2][8][4];
    #pragma unroll
    for (int mt = 0; mt < 2; mt++)
        #pragma unroll
        for (int nt = 0; nt < 8; nt++)
            #pragma unroll
            for (int j = 0; j < 4; j++) acc[mt][nt][j] = 0.f;

    for (int n = 0; n < 9; n++) {
        int s = n & 1;
        if (wid < 4) {
            // ---- producer: stage B(n+1) + sample(n+1) into 1-s ----
            if (n < 8) {
                int ns = 1 - s;
                const uint4* sh = (const uint4*)g_wbhi + (n + 1) * 512;
                const uint4* sl = (const uint4*)g_wblo + (n + 1) * 512;
                #pragma unroll
                for (int j = 0; j < 4; j++) {
                    ((uint4*)(smc + BHI(ns)))[t + j * 128] = sh[t + j * 128];
                    ((uint4*)(smc + BLO(ns)))[t + j * 128] = sl[t + j * 128];
                }
                #pragma unroll
                for (int i = 0; i < 8; i++) {
                    int lp = wid * 32 + i * 4 + g4;
                    sample_pix(xb, mo, mw, lp, n + 1, l8, sb + AHI(ns), sb + ALO(ns));
                }
            }
        } else {
            // ---- consumer: mma(n) from stage s; warp = 32 pixels x 64 oc ----
            int mbase = (wid - 4) * 32;
            u32 aHiB = sb + AHI(s), aLoB = sb + ALO(s);
            u32 bHiB = sb + BHI(s), bLoB = sb + BLO(s);
            u32 arow = (u32)((mbase + (ln & 15)) * 128 + ((ln >> 4) * 16));
            u32 brow = (u32)(((((ln >> 4) << 3) + (ln & 7))) * 128 + (((ln >> 3) & 1) * 16));
            #pragma unroll
            for (int k = 0; k < 4; k++) {
                u32 ka = (u32)(k * 32);
                u32 ah[8], al[8], bh[16], bl[16];
                ldsm4(aHiB + swz(arow + ka),        ah[0], ah[1], ah[2], ah[3]);
                ldsm4(aHiB + swz(arow + 2048 + ka), ah[4], ah[5], ah[6], ah[7]);
                ldsm4(aLoB + swz(arow + ka),        al[0], al[1], al[2], al[3]);
                ldsm4(aLoB + swz(arow + 2048 + ka), al[4], al[5], al[6], al[7]);
                #pragma unroll
                for (int g = 0; g < 4; g++) {
                    ldsm4(bHiB + swz(brow + g * 2048 + ka), bh[g*4], bh[g*4+1], bh[g*4+2], bh[g*4+3]);
                    ldsm4(bLoB + swz(brow + g * 2048 + ka), bl[g*4], bl[g*4+1], bl[g*4+2], bl[g*4+3]);
                }
                #pragma unroll
                for (int mt = 0; mt < 2; mt++) {
                    #pragma unroll
                    for (int nt = 0; nt < 8; nt++) {
                        mma_bf16(acc[mt][nt][0], acc[mt][nt][1], acc[mt][nt][2], acc[mt][nt][3],
                                 ah[mt*4], ah[mt*4+1], ah[mt*4+2], ah[mt*4+3], bh[nt*2], bh[nt*2+1]);
                        mma_bf16(acc[mt][nt][0], acc[mt][nt][1], acc[mt][nt][2], acc[mt][nt][3],
                                 al[mt*4], al[mt*4+1], al[mt*4+2], al[mt*4+3], bh[nt*2], bh[nt*2+1]);
                        mma_bf16(acc[mt][nt][0], acc[mt][nt][1], acc[mt][nt][2], acc[mt][nt][3],
                                 ah[mt*4], ah[mt*4+1], ah[mt*4+2], ah[mt*4+3], bl[nt*2], bl[nt*2+1]);
                    }
                }
            }
        }
        __syncthreads();
    }

    // ========== epilogue (consumers hold the results) ==========
    if (wid >= 4) {
        int mbase = (wid - 4) * 32;
        #pragma unroll
        for (int mt = 0; mt < 2; mt++) {
            #pragma unroll
            for (int nt = 0; nt < 8; nt++) {
                int pix = p0 + mbase + mt * 16 + (ln >> 2);
                int oc  = nt * 8 + (ln & 3) * 2;
                float b0 = __ldg(bker + oc), b1 = __ldg(bker + oc + 1);
                size_t base = ((size_t)(b * 64 + oc)) * NPIX + pix;
                out[base]            = acc[mt][nt][0] + b0;
                out[base + NPIX]     = acc[mt][nt][1] + b1;
                out[base + 8]        = acc[mt][nt][2] + b0;
                out[base + NPIX + 8] = acc[mt][nt][3] + b1;
            }
        }
    }
}

// ================= launch =================
extern "C" void kernel_launch(void* const* d_in, const int* in_sizes, int n_in,
                              void* d_out, int out_size) {
    const float* x     = (const float*)d_in[0];
    const float* w_off = (const float*)d_in[1];
    const float* b_off = (const float*)d_in[2];
    const float* w_ker = (const float*)d_in[3];
    const float* b_ker = (const float*)d_in[4];
    float* out = (float*)d_out;

    cudaFuncSetAttribute(k_main, cudaFuncAttributeMaxDynamicSharedMemorySize, SMEM_MAIN);

    k_transpose<<<dim3(NPIX / 64, BB), 256>>>(x);
    k_prep<<<(9 * 4096 + 9 * 2048 + 255) / 256, 256>>>(w_ker, w_off);
    k_main<<<dim3(NPIX / 128, BB), 256, SMEM_MAIN>>>(b_off, b_ker, out);
}

// round 8
// speedup vs baseline: 1.1390x; 1.1390x over previous
#include <cuda_runtime.h>
#include <cuda_bf16.h>

// ---------------- constants ----------------
#define HH 96
#define WW 96
#define NPIX 9216
#define BB 8

typedef unsigned int u32;
typedef unsigned long long ull;

// ---------------- scratch ----------------
__device__ float g_xt[BB * NPIX * 64];            // x channels-last f32
__device__ unsigned short g_wbhi[9 * 64 * 64];    // main-conv B bf16 hi, swizzled [n][oc][ch]
__device__ unsigned short g_wblo[9 * 64 * 64];
__device__ unsigned short g_wobhi[9 * 32 * 64];   // offset-conv B (24 rows used, padded 32)
__device__ unsigned short g_woblo[9 * 32 * 64];

// ---------------- helpers ----------------
__device__ __forceinline__ u32 s2u(const void* p) {
    u32 a; asm("{ .reg .u64 t; cvta.to.shared.u64 t, %1; cvt.u32.u64 %0, t; }" : "=r"(a) : "l"(p));
    return a;
}
__device__ __forceinline__ u32 swz(u32 b) { return b ^ ((b >> 3) & 0x70); }

__device__ __forceinline__ void ldsm4(u32 a, u32& r0, u32& r1, u32& r2, u32& r3) {
    asm volatile("ldmatrix.sync.aligned.m8n8.x4.shared.b16 {%0,%1,%2,%3}, [%4];"
                 : "=r"(r0), "=r"(r1), "=r"(r2), "=r"(r3) : "r"(a));
}
__device__ __forceinline__ void mma_bf16(float& d0, float& d1, float& d2, float& d3,
                                         u32 a0, u32 a1, u32 a2, u32 a3, u32 b0, u32 b1) {
    asm volatile("mma.sync.aligned.m16n8k16.row.col.f32.bf16.bf16.f32 "
                 "{%0,%1,%2,%3},{%4,%5,%6,%7},{%8,%9},{%0,%1,%2,%3};"
                 : "+f"(d0), "+f"(d1), "+f"(d2), "+f"(d3)
                 : "r"(a0), "r"(a1), "r"(a2), "r"(a3), "r"(b0), "r"(b1));
}
__device__ __forceinline__ void sts128(u32 a, u32 x, u32 y, u32 z, u32 w) {
    asm volatile("st.shared.v4.b32 [%0],{%1,%2,%3,%4};" :: "r"(a), "r"(x), "r"(y), "r"(z), "r"(w) : "memory");
}
__device__ __forceinline__ u32 bfhi2(float a, float b) {
    return __byte_perm(__float_as_uint(a), __float_as_uint(b), 0x7632);
}
__device__ __forceinline__ u32 bflo2(float a, float b) {
    float la = a - __uint_as_float(__float_as_uint(a) & 0xFFFF0000u);
    float lb = b - __uint_as_float(__float_as_uint(b) & 0xFFFF0000u);
    u32 r; asm("cvt.rn.bf16x2.f32 %0, %1, %2;" : "=r"(r) : "f"(lb), "f"(la));
    return r;
}
__device__ __forceinline__ ull pack2(float lo, float hi) {
    ull r; asm("mov.b64 %0, {%1,%2};" : "=l"(r) : "f"(lo), "f"(hi)); return r;
}
__device__ __forceinline__ void unpack2(ull v, float& lo, float& hi) {
    asm("mov.b64 {%0,%1}, %2;" : "=f"(lo), "=f"(hi) : "l"(v));
}
__device__ __forceinline__ ull mul2(ull a, ull b) {
    ull r; asm("mul.rn.f32x2 %0, %1, %2;" : "=l"(r) : "l"(a), "l"(b)); return r;
}
__device__ __forceinline__ void fma2(ull& d, ull a, ull b) {
    asm("fma.rn.f32x2 %0, %1, %2, %0;" : "+l"(d) : "l"(a), "l"(b));
}

// ================= K1: transpose x (b,c,h,w) -> (b,hw,c) =================
__global__ __launch_bounds__(256) void k_transpose(const float* __restrict__ x) {
    __shared__ float tile[64][65];
    int b  = blockIdx.y;
    int p0 = blockIdx.x << 6;
    int t  = threadIdx.x;
    #pragma unroll
    for (int i = t; i < 4096; i += 256) {
        int c = i >> 6, p = i & 63;
        tile[c][p] = x[((size_t)(b * 64 + c)) * NPIX + p0 + p];
    }
    __syncthreads();
    #pragma unroll
    for (int i = t; i < 4096; i += 256) {
        int p = i >> 6, c = i & 63;
        g_xt[((size_t)b * NPIX + p0 + p) * 64 + c] = tile[c][p];
    }
}

// ================= K0: weight prep =================
__global__ __launch_bounds__(256) void k_prep(const float* __restrict__ wker,
                                              const float* __restrict__ wof) {
    int i = blockIdx.x * 256 + threadIdx.x;
    if (i < 9 * 4096) {
        int n = i >> 12, r = i & 4095, oc = r >> 6, ch = r & 63;
        float v = wker[(oc * 64 + ch) * 9 + n];
        u32 hib = __float_as_uint(v) & 0xFFFF0000u;
        float lv = v - __uint_as_float(hib);
        __nv_bfloat16 lb = __float2bfloat16(lv);
        u32 sw = swz((u32)(oc * 128 + ch * 2)) >> 1;
        g_wbhi[n * 4096 + sw] = (unsigned short)(hib >> 16);
        g_wblo[n * 4096 + sw] = *(unsigned short*)&lb;
    } else {
        int j = i - 9 * 4096;
        if (j < 9 * 2048) {
            int n = j >> 11, r = j & 2047, oc = r >> 6, ch = r & 63;
            float v = (oc < 18) ? wof[(oc * 64 + ch) * 9 + n] : 0.f;
            u32 hib = __float_as_uint(v) & 0xFFFF0000u;
            float lv = v - __uint_as_float(hib);
            __nv_bfloat16 lb = __float2bfloat16(lv);
            u32 sw = swz((u32)(oc * 128 + ch * 2)) >> 1;
            g_wobhi[n * 2048 + sw] = (unsigned short)(hib >> 16);
            g_woblo[n * 2048 + sw] = *(unsigned short*)&lb;
        }
    }
}

// ================= K_MAIN =================
// smem: A ring 2 x (16K hi + 16K lo) = 64K, B ring 2 x (8K hi + 8K lo) = 32K,
//       meta compressed: mxy (int, 4.5K) + mlxy (float2, 9K)  -> 112128 total
#define AHI(s)  ((s) * 32768)
#define ALO(s)  ((s) * 32768 + 16384)
#define BHI(s)  (65536 + (s) * 16384)
#define BLO(s)  (65536 + (s) * 16384 + 8192)
#define OFF_MXY  98304
#define OFF_MLXY 102912
#define SMEM_MAIN 112128

// sample one pixel's 8-channel slice (lane l8) for point n into stage tiles
__device__ __forceinline__ void sample_pix(const float* __restrict__ xb,
                                           const int* __restrict__ mxy,
                                           const float2* __restrict__ mlxy,
                                           int lp, int n, int l8,
                                           u32 aHiB, u32 aLoB) {
    int mi = lp * 9 + n;
    int xy = mxy[mi];
    float2 l = mlxy[mi];
    int x0 = xy >> 16, y0 = (xy << 16) >> 16;
    int x1 = x0 + 1, y1 = y0 + 1;
    float lx = l.x, ly = l.y;
    float w00 = (1.f - lx) * (1.f - ly);
    float w10 = lx * (1.f - ly);
    float w01 = (1.f - lx) * ly;
    float w11 = lx * ly;
    if ((unsigned)x0 >= 96u) { w00 = 0.f; w01 = 0.f; }
    if ((unsigned)x1 >= 96u) { w10 = 0.f; w11 = 0.f; }
    if ((unsigned)y0 >= 96u) { w00 = 0.f; w10 = 0.f; }
    if ((unsigned)y1 >= 96u) { w01 = 0.f; w11 = 0.f; }
    int cx0 = min(max(x0, 0), 95), cx1 = min(max(x1, 0), 95);
    int cy0 = min(max(y0, 0), 95), cy1 = min(max(y1, 0), 95);
    const float* pA = xb + (cx0 * 96 + cy0) * 64 + l8 * 8;
    const float* pB = xb + (cx1 * 96 + cy0) * 64 + l8 * 8;
    const float* pC = xb + (cx0 * 96 + cy1) * 64 + l8 * 8;
    const float* pD = xb + (cx1 * 96 + cy1) * 64 + l8 * 8;
    float4 A0 = *(const float4*)pA, A1 = *(const float4*)(pA + 4);
    float4 B0 = *(const float4*)pB, B1 = *(const float4*)(pB + 4);
    float4 C0 = *(const float4*)pC, C1 = *(const float4*)(pC + 4);
    float4 D0 = *(const float4*)pD, D1 = *(const float4*)(pD + 4);
    ull W00 = pack2(w00, w00), W10 = pack2(w10, w10);
    ull W01 = pack2(w01, w01), W11 = pack2(w11, w11);
    ull r0 = mul2(pack2(A0.x, A0.y), W00);
    ull r1 = mul2(pack2(A0.z, A0.w), W00);
    ull r2 = mul2(pack2(A1.x, A1.y), W00);
    ull r3 = mul2(pack2(A1.z, A1.w), W00);
    fma2(r0, pack2(B0.x, B0.y), W10); fma2(r1, pack2(B0.z, B0.w), W10);
    fma2(r2, pack2(B1.x, B1.y), W10); fma2(r3, pack2(B1.z, B1.w), W10);
    fma2(r0, pack2(C0.x, C0.y), W01); fma2(r1, pack2(C0.z, C0.w), W01);
    fma2(r2, pack2(C1.x, C1.y), W01); fma2(r3, pack2(C1.z, C1.w), W01);
    fma2(r0, pack2(D0.x, D0.y), W11); fma2(r1, pack2(D0.z, D0.w), W11);
    fma2(r2, pack2(D1.x, D1.y), W11); fma2(r3, pack2(D1.z, D1.w), W11);
    float s0, s1, s2, s3, s4, s5, s6, s7;
    unpack2(r0, s0, s1); unpack2(r1, s2, s3);
    unpack2(r2, s4, s5); unpack2(r3, s6, s7);
    u32 sa = swz((u32)(lp * 128 + l8 * 16));
    sts128(aHiB + sa, bfhi2(s0, s1), bfhi2(s2, s3), bfhi2(s4, s5), bfhi2(s6, s7));
    sts128(aLoB + sa, bflo2(s0, s1), bflo2(s2, s3), bflo2(s4, s5), bflo2(s6, s7));
}

__global__ __launch_bounds__(256, 2) void k_main(const float* __restrict__ bof,
                                                 const float* __restrict__ bker,
                                                 float* __restrict__ out) {
    extern __shared__ char smc[];
    u32 sb = s2u(smc);
    int t = threadIdx.x, wid = t >> 5, ln = t & 31;
    int b = blockIdx.y;
    int p0 = blockIdx.x * 128;
    const float* xb = g_xt + (size_t)b * NPIX * 64;

    // ========== PHASE 0: offset conv (3-term hi/lo split), all 8 warps ==========
    float acc0[3][4];
    #pragma unroll
    for (int nt = 0; nt < 3; nt++)
        #pragma unroll
        for (int j = 0; j < 4; j++) acc0[nt][j] = 0.f;

    {
        int lp = t >> 1, q = t & 1;
        int pix = p0 + lp, hh = pix / 96, ww = pix - hh * 96;
        u32 aHiB = sb + AHI(0), aLoB = sb + ALO(0);

        for (int tap = 0; tap < 9; tap++) {
            __syncthreads();
            ((uint4*)(smc + BHI(0)))[t] = ((const uint4*)g_wobhi + tap * 256)[t];
            ((uint4*)(smc + BLO(0)))[t] = ((const uint4*)g_woblo + tap * 256)[t];
            // A-build (hi + lo residual) from f32 channels-last
            {
                int sh_ = hh + tap / 3 - 1, sw_ = ww + tap % 3 - 1;
                bool ok = ((unsigned)sh_ < 96u) & ((unsigned)sw_ < 96u);
                float4 v[8];
                if (ok) {
                    const float4* src = (const float4*)(xb + (size_t)(sh_ * 96 + sw_) * 64) + q * 8;
                    #pragma unroll
                    for (int j = 0; j < 8; j++) v[j] = src[j];
                } else {
                    #pragma unroll
                    for (int j = 0; j < 8; j++) v[j] = make_float4(0.f, 0.f, 0.f, 0.f);
                }
                u32 rowb = (u32)(lp * 128 + q * 64);
                #pragma unroll
                for (int j = 0; j < 4; j++) {
                    u32 sa = swz(rowb + j * 16);
                    sts128(aHiB + sa, bfhi2(v[2*j].x, v[2*j].y), bfhi2(v[2*j].z, v[2*j].w),
                                      bfhi2(v[2*j+1].x, v[2*j+1].y), bfhi2(v[2*j+1].z, v[2*j+1].w));
                    sts128(aLoB + sa, bflo2(v[2*j].x, v[2*j].y), bflo2(v[2*j].z, v[2*j].w),
                                      bflo2(v[2*j+1].x, v[2*j+1].y), bflo2(v[2*j+1].z, v[2*j+1].w));
                }
            }
            __syncthreads();
            {
                u32 arow = (u32)((wid * 16 + (ln & 15)) * 128 + ((ln >> 4) * 16));
                u32 brow = (u32)(((((ln >> 4) << 3) + (ln & 7))) * 128 + (((ln >> 3) & 1) * 16));
                u32 bHiB = sb + BHI(0), bLoB = sb + BLO(0);
                #pragma unroll
                for (int k = 0; k < 4; k++) {
                    u32 ka = (u32)(k * 32);
                    u32 ah[4], al[4], bh[8], bl[8];
                    ldsm4(aHiB + swz(arow + ka), ah[0], ah[1], ah[2], ah[3]);
                    ldsm4(aLoB + swz(arow + ka), al[0], al[1], al[2], al[3]);
                    ldsm4(bHiB + swz(brow + ka), bh[0], bh[1], bh[2], bh[3]);
                    ldsm4(bHiB + swz(brow + 2048 + ka), bh[4], bh[5], bh[6], bh[7]);
                    ldsm4(bLoB + swz(brow + ka), bl[0], bl[1], bl[2], bl[3]);
                    ldsm4(bLoB + swz(brow + 2048 + ka), bl[4], bl[5], bl[6], bl[7]);
                    #pragma unroll
                    for (int nt = 0; nt < 3; nt++) {
                        mma_bf16(acc0[nt][0], acc0[nt][1], acc0[nt][2], acc0[nt][3],
                                 ah[0], ah[1], ah[2], ah[3], bh[nt*2], bh[nt*2+1]);
                        mma_bf16(acc0[nt][0], acc0[nt][1], acc0[nt][2], acc0[nt][3],
                                 al[0], al[1], al[2], al[3], bh[nt*2], bh[nt*2+1]);
                        mma_bf16(acc0[nt][0], acc0[nt][1], acc0[nt][2], acc0[nt][3],
                                 ah[0], ah[1], ah[2], ah[3], bl[nt*2], bl[nt*2+1]);
                    }
                }
            }
        }
    }
    __syncthreads();
    {
        float* dst = (float*)(smc + AHI(0));
        int pr = wid * 16 + (ln >> 2);
        int pc = (ln & 3) * 2;
        #pragma unroll
        for (int nt = 0; nt < 3; nt++) {
            dst[pr * 24 + nt * 8 + pc]           = acc0[nt][0];
            dst[pr * 24 + nt * 8 + pc + 1]       = acc0[nt][1];
            dst[(pr + 8) * 24 + nt * 8 + pc]     = acc0[nt][2];
            dst[(pr + 8) * 24 + nt * 8 + pc + 1] = acc0[nt][3];
        }
    }
    __syncthreads();
    {
        const float* dsm = (const float*)(smc + AHI(0));
        int*    mxy  = (int*)(smc + OFF_MXY);
        float2* mlxy = (float2*)(smc + OFF_MLXY);
        for (int i = t; i < 1152; i += 256) {
            int lp = i / 9, n = i - lp * 9;
            int pix = p0 + lp, hh = pix / 96, ww = pix - hh * 96;
            float ox = dsm[lp * 24 + n]     + __ldg(bof + n);
            float oy = dsm[lp * 24 + 9 + n] + __ldg(bof + 9 + n);
            float px = (float)(hh + n / 3 - 1) + ox;
            float py = (float)(ww + n % 3 - 1) + oy;
            px = fminf(fmaxf(px, -10000.f), 10000.f);
            py = fminf(fmaxf(py, -10000.f), 10000.f);
            float fx = floorf(px), fy = floorf(py);
            int x0 = (int)fx, y0 = (int)fy;
            mxy[i]  = (x0 << 16) | (y0 & 0xffff);
            mlxy[i] = make_float2(px - fx, py - fy);
        }
    }
    __syncthreads();

    // ========== PHASE 1: double-buffered, one barrier per n, homogeneous warps ==========
    const int*    mxy  = (const int*)(smc + OFF_MXY);
    const float2* mlxy = (const float2*)(smc + OFF_MLXY);
    int l8 = ln & 7, g4 = ln >> 3;

    // prologue: stage B(0) + sample(0) into stage 0
    {
        const uint4* sh = (const uint4*)g_wbhi;   // n = 0
        const uint4* sl = (const uint4*)g_wblo;
        ((uint4*)(smc + BHI(0)))[t]       = sh[t];
        ((uint4*)(smc + BHI(0)))[t + 256] = sh[t + 256];
        ((uint4*)(smc + BLO(0)))[t]       = sl[t];
        ((uint4*)(smc + BLO(0)))[t + 256] = sl[t + 256];
        #pragma unroll
        for (int i = 0; i < 4; i++) {
            int lp = wid * 16 + i * 4 + g4;
            sample_pix(xb, mxy, mlxy, lp, 0, l8, sb + AHI(0), sb + ALO(0));
        }
    }
    __syncthreads();

    float acc[2][4][4];
    #pragma unroll
    for (int mt = 0; mt < 2; mt++)
        #pragma unroll
        for (int nt = 0; nt < 4; nt++)
            #pragma unroll
            for (int j = 0; j < 4; j++) acc[mt][nt][j] = 0.f;

    int mbase = (wid & 3) * 32, nbase = (wid >> 2) * 32;
    u32 arow = (u32)((mbase + (ln & 15)) * 128 + ((ln >> 4) * 16));
    u32 brow = (u32)((nbase + ((ln >> 4) << 3) + (ln & 7)) * 128 + (((ln >> 3) & 1) * 16));

    for (int n = 0; n < 9; n++) {
        int s = n & 1, ns = 1 - s;
        // producer half of the body: stage next B + next samples (LDGs issue early,
        // STS lands while mma below streams from the current stage)
        if (n < 8) {
            const uint4* sh = (const uint4*)g_wbhi + (n + 1) * 512;
            const uint4* sl = (const uint4*)g_wblo + (n + 1) * 512;
            ((uint4*)(smc + BHI(ns)))[t]       = sh[t];
            ((uint4*)(smc + BHI(ns)))[t + 256] = sh[t + 256];
            ((uint4*)(smc + BLO(ns)))[t]       = sl[t];
            ((uint4*)(smc + BLO(ns)))[t + 256] = sl[t + 256];
            #pragma unroll
            for (int i = 0; i < 4; i++) {
                int lp = wid * 16 + i * 4 + g4;
                sample_pix(xb, mxy, mlxy, lp, n + 1, l8, sb + AHI(ns), sb + ALO(ns));
            }
        }
        // consumer half: mma(n) from stage s
        {
            u32 aHiB = sb + AHI(s), aLoB = sb + ALO(s);
            u32 bHiB = sb + BHI(s), bLoB = sb + BLO(s);
            #pragma unroll
            for (int k = 0; k < 4; k++) {
                u32 ka = (u32)(k * 32);
                u32 ah[8], al[8], bh[8], bl[8];
                ldsm4(aHiB + swz(arow + ka),        ah[0], ah[1], ah[2], ah[3]);
                ldsm4(aHiB + swz(arow + 2048 + ka), ah[4], ah[5], ah[6], ah[7]);
                ldsm4(aLoB + swz(arow + ka),        al[0], al[1], al[2], al[3]);
                ldsm4(aLoB + swz(arow + 2048 + ka), al[4], al[5], al[6], al[7]);
                ldsm4(bHiB + swz(brow + ka),        bh[0], bh[1], bh[2], bh[3]);
                ldsm4(bHiB + swz(brow + 2048 + ka), bh[4], bh[5], bh[6], bh[7]);
                ldsm4(bLoB + swz(brow + ka),        bl[0], bl[1], bl[2], bl[3]);
                ldsm4(bLoB + swz(brow + 2048 + ka), bl[4], bl[5], bl[6], bl[7]);
                #pragma unroll
                for (int mt = 0; mt < 2; mt++) {
                    #pragma unroll
                    for (int nt = 0; nt < 4; nt++) {
                        mma_bf16(acc[mt][nt][0], acc[mt][nt][1], acc[mt][nt][2], acc[mt][nt][3],
                                 ah[mt*4], ah[mt*4+1], ah[mt*4+2], ah[mt*4+3], bh[nt*2], bh[nt*2+1]);
                        mma_bf16(acc[mt][nt][0], acc[mt][nt][1], acc[mt][nt][2], acc[mt][nt][3],
                                 al[mt*4], al[mt*4+1], al[mt*4+2], al[mt*4+3], bh[nt*2], bh[nt*2+1]);
                        mma_bf16(acc[mt][nt][0], acc[mt][nt][1], acc[mt][nt][2], acc[mt][nt][3],
                                 ah[mt*4], ah[mt*4+1], ah[mt*4+2], ah[mt*4+3], bl[nt*2], bl[nt*2+1]);
                    }
                }
            }
        }
        __syncthreads();
    }

    // ========== epilogue ==========
    {
        #pragma unroll
        for (int mt = 0; mt < 2; mt++) {
            #pragma unroll
            for (int nt = 0; nt < 4; nt++) {
                int pix = p0 + mbase + mt * 16 + (ln >> 2);
                int oc  = nbase + nt * 8 + (ln & 3) * 2;
                float b0 = __ldg(bker + oc), b1 = __ldg(bker + oc + 1);
                size_t base = ((size_t)(b * 64 + oc)) * NPIX + pix;
                out[base]            = acc[mt][nt][0] + b0;
                out[base + NPIX]     = acc[mt][nt][1] + b1;
                out[base + 8]        = acc[mt][nt][2] + b0;
                out[base + NPIX + 8] = acc[mt][nt][3] + b1;
            }
        }
    }
}

// ================= launch =================
extern "C" void kernel_launch(void* const* d_in, const int* in_sizes, int n_in,
                              void* d_out, int out_size) {
    const float* x     = (const float*)d_in[0];
    const float* w_off = (const float*)d_in[1];
    const float* b_off = (const float*)d_in[2];
    const float* w_ker = (const float*)d_in[3];
    const float* b_ker = (const float*)d_in[4];
    float* out = (float*)d_out;

    cudaFuncSetAttribute(k_main, cudaFuncAttributeMaxDynamicSharedMemorySize, SMEM_MAIN);

    k_transpose<<<dim3(NPIX / 64, BB), 256>>>(x);
    k_prep<<<(9 * 4096 + 9 * 2048 + 255) / 256, 256>>>(w_ker, w_off);
    k_main<<<dim3(NPIX / 128, BB), 256, SMEM_MAIN>>>(b_off, b_ker, out);
}

// round 10
// speedup vs baseline: 1.1688x; 1.0262x over previous
#include <cuda_runtime.h>
#include <cuda_bf16.h>

// ---------------- constants ----------------
#define HH 96
#define WW 96
#define NPIX 9216
#define BB 8

typedef unsigned int u32;
typedef unsigned long long ull;

// ---------------- scratch ----------------
__device__ float g_xt[BB * NPIX * 64];            // x channels-last f32
__device__ unsigned short g_wbhi[9 * 64 * 64];    // main-conv B bf16 hi, swizzled [n][oc][ch]
__device__ unsigned short g_wblo[9 * 64 * 64];
__device__ unsigned short g_wobhi[9 * 32 * 64];   // offset-conv B (24 rows used, padded 32)
__device__ unsigned short g_woblo[9 * 32 * 64];
__device__ int    g_mxy[BB * NPIX * 9];           // packed (x0<<16)|y0
__device__ float2 g_mlxy[BB * NPIX * 9];          // (lx, ly)

// ---------------- helpers ----------------
__device__ __forceinline__ u32 s2u(const void* p) {
    u32 a; asm("{ .reg .u64 t; cvta.to.shared.u64 t, %1; cvt.u32.u64 %0, t; }" : "=r"(a) : "l"(p));
    return a;
}
__device__ __forceinline__ u32 swz(u32 b) { return b ^ ((b >> 3) & 0x70); }

__device__ __forceinline__ void ldsm4(u32 a, u32& r0, u32& r1, u32& r2, u32& r3) {
    asm volatile("ldmatrix.sync.aligned.m8n8.x4.shared.b16 {%0,%1,%2,%3}, [%4];"
                 : "=r"(r0), "=r"(r1), "=r"(r2), "=r"(r3) : "r"(a));
}
__device__ __forceinline__ void mma_bf16(float& d0, float& d1, float& d2, float& d3,
                                         u32 a0, u32 a1, u32 a2, u32 a3, u32 b0, u32 b1) {
    asm volatile("mma.sync.aligned.m16n8k16.row.col.f32.bf16.bf16.f32 "
                 "{%0,%1,%2,%3},{%4,%5,%6,%7},{%8,%9},{%0,%1,%2,%3};"
                 : "+f"(d0), "+f"(d1), "+f"(d2), "+f"(d3)
                 : "r"(a0), "r"(a1), "r"(a2), "r"(a3), "r"(b0), "r"(b1));
}
__device__ __forceinline__ void sts128(u32 a, u32 x, u32 y, u32 z, u32 w) {
    asm volatile("st.shared.v4.b32 [%0],{%1,%2,%3,%4};" :: "r"(a), "r"(x), "r"(y), "r"(z), "r"(w) : "memory");
}
__device__ __forceinline__ u32 bfhi2(float a, float b) {
    return __byte_perm(__float_as_uint(a), __float_as_uint(b), 0x7632);
}
__device__ __forceinline__ u32 bflo2(float a, float b) {
    float la = a - __uint_as_float(__float_as_uint(a) & 0xFFFF0000u);
    float lb = b - __uint_as_float(__float_as_uint(b) & 0xFFFF0000u);
    u32 r; asm("cvt.rn.bf16x2.f32 %0, %1, %2;" : "=r"(r) : "f"(lb), "f"(la));
    return r;
}
__device__ __forceinline__ ull pack2(float lo, float hi) {
    ull r; asm("mov.b64 %0, {%1,%2};" : "=l"(r) : "f"(lo), "f"(hi)); return r;
}
__device__ __forceinline__ void unpack2(ull v, float& lo, float& hi) {
    asm("mov.b64 {%0,%1}, %2;" : "=f"(lo), "=f"(hi) : "l"(v));
}
__device__ __forceinline__ ull mul2(ull a, ull b) {
    ull r; asm("mul.rn.f32x2 %0, %1, %2;" : "=l"(r) : "l"(a), "l"(b)); return r;
}
__device__ __forceinline__ void fma2(ull& d, ull a, ull b) {
    asm("fma.rn.f32x2 %0, %1, %2, %0;" : "+l"(d) : "l"(a), "l"(b));
}

// ================= K_AUX: transpose (x<144) + weight prep (x>=144) =================
__global__ __launch_bounds__(256) void k_aux(const float* __restrict__ x,
                                             const float* __restrict__ wker,
                                             const float* __restrict__ wof) {
    int bx = blockIdx.x, b = blockIdx.y;
    int t = threadIdx.x;
    if (bx < 144) {
        __shared__ float tile[64][65];
        int p0 = bx << 6;
        #pragma unroll
        for (int i = t; i < 4096; i += 256) {
            int c = i >> 6, p = i & 63;
            tile[c][p] = x[((size_t)(b * 64 + c)) * NPIX + p0 + p];
        }
        __syncthreads();
        #pragma unroll
        for (int i = t; i < 4096; i += 256) {
            int p = i >> 6, c = i & 63;
            g_xt[((size_t)b * NPIX + p0 + p) * 64 + c] = tile[c][p];
        }
    } else {
        int i = ((bx - 144) + 27 * b) * 256 + t;
        if (i < 9 * 4096) {
            int n = i >> 12, r = i & 4095, oc = r >> 6, ch = r & 63;
            float v = wker[(oc * 64 + ch) * 9 + n];
            u32 hib = __float_as_uint(v) & 0xFFFF0000u;
            float lv = v - __uint_as_float(hib);
            __nv_bfloat16 lb = __float2bfloat16(lv);
            u32 sw = swz((u32)(oc * 128 + ch * 2)) >> 1;
            g_wbhi[n * 4096 + sw] = (unsigned short)(hib >> 16);
            g_wblo[n * 4096 + sw] = *(unsigned short*)&lb;
        } else {
            int j = i - 9 * 4096;
            if (j < 9 * 2048) {
                int n = j >> 11, r = j & 2047, oc = r >> 6, ch = r & 63;
                float v = (oc < 18) ? wof[(oc * 64 + ch) * 9 + n] : 0.f;
                u32 hib = __float_as_uint(v) & 0xFFFF0000u;
                float lv = v - __uint_as_float(hib);
                __nv_bfloat16 lb = __float2bfloat16(lv);
                u32 sw = swz((u32)(oc * 128 + ch * 2)) >> 1;
                g_wobhi[n * 2048 + sw] = (unsigned short)(hib >> 16);
                g_woblo[n * 2048 + sw] = *(unsigned short*)&lb;
            }
        }
    }
}

// ================= K_OFF: offset conv + bilinear meta -> gmem =================
// smem: A_HI 16K, A_LO 16K, B_HI 4K, B_LO 4K  (A region reused for f32 results)
#define O_AHI 0
#define O_ALO 16384
#define O_BHI 32768
#define O_BLO 36864
#define SMEM_OFFK 40960

__global__ __launch_bounds__(256, 2) void k_off(const float* __restrict__ bof) {
    extern __shared__ char smc[];
    u32 sb = s2u(smc);
    int t = threadIdx.x, wid = t >> 5, ln = t & 31;
    int b = blockIdx.y;
    int p0 = blockIdx.x * 128;
    const float* xb = g_xt + (size_t)b * NPIX * 64;

    float acc0[3][4];
    #pragma unroll
    for (int nt = 0; nt < 3; nt++)
        #pragma unroll
        for (int j = 0; j < 4; j++) acc0[nt][j] = 0.f;

    {
        int lp = t >> 1, q = t & 1;
        int pix = p0 + lp, hh = pix / 96, ww = pix - hh * 96;
        u32 aHiB = sb + O_AHI, aLoB = sb + O_ALO;

        for (int tap = 0; tap < 9; tap++) {
            __syncthreads();
            ((uint4*)(smc + O_BHI))[t] = ((const uint4*)g_wobhi)[tap * 256 + t];
            ((uint4*)(smc + O_BLO))[t] = ((const uint4*)g_woblo)[tap * 256 + t];
            {
                int sh_ = hh + tap / 3 - 1, sw_ = ww + tap % 3 - 1;
                bool ok = ((unsigned)sh_ < 96u) & ((unsigned)sw_ < 96u);
                float4 v[8];
                if (ok) {
                    const float4* src = (const float4*)(xb + (size_t)(sh_ * 96 + sw_) * 64) + q * 8;
                    #pragma unroll
                    for (int j = 0; j < 8; j++) v[j] = src[j];
                } else {
                    #pragma unroll
                    for (int j = 0; j < 8; j++) v[j] = make_float4(0.f, 0.f, 0.f, 0.f);
                }
                u32 rowb = (u32)(lp * 128 + q * 64);
                #pragma unroll
                for (int j = 0; j < 4; j++) {
                    u32 sa = swz(rowb + j * 16);
                    sts128(aHiB + sa, bfhi2(v[2*j].x, v[2*j].y), bfhi2(v[2*j].z, v[2*j].w),
                                      bfhi2(v[2*j+1].x, v[2*j+1].y), bfhi2(v[2*j+1].z, v[2*j+1].w));
                    sts128(aLoB + sa, bflo2(v[2*j].x, v[2*j].y), bflo2(v[2*j].z, v[2*j].w),
                                      bflo2(v[2*j+1].x, v[2*j+1].y), bflo2(v[2*j+1].z, v[2*j+1].w));
                }
            }
            __syncthreads();
            {
                u32 arow = (u32)((wid * 16 + (ln & 15)) * 128 + ((ln >> 4) * 16));
                u32 brow = (u32)(((((ln >> 4) << 3) + (ln & 7))) * 128 + (((ln >> 3) & 1) * 16));
                u32 bHiB = sb + O_BHI, bLoB = sb + O_BLO;
                #pragma unroll
                for (int k = 0; k < 4; k++) {
                    u32 ka = (u32)(k * 32);
                    u32 ah[4], al[4], bh[8], bl[8];
                    ldsm4(aHiB + swz(arow + ka), ah[0], ah[1], ah[2], ah[3]);
                    ldsm4(aLoB + swz(arow + ka), al[0], al[1], al[2], al[3]);
                    ldsm4(bHiB + swz(brow + ka), bh[0], bh[1], bh[2], bh[3]);
                    ldsm4(bHiB + swz(brow + 2048 + ka), bh[4], bh[5], bh[6], bh[7]);
                    ldsm4(bLoB + swz(brow + ka), bl[0], bl[1], bl[2], bl[3]);
                    ldsm4(bLoB + swz(brow + 2048 + ka), bl[4], bl[5], bl[6], bl[7]);
                    #pragma unroll
                    for (int nt = 0; nt < 3; nt++) {
                        mma_bf16(acc0[nt][0], acc0[nt][1], acc0[nt][2], acc0[nt][3],
                                 ah[0], ah[1], ah[2], ah[3], bh[nt*2], bh[nt*2+1]);
                        mma_bf16(acc0[nt][0], acc0[nt][1], acc0[nt][2], acc0[nt][3],
                                 al[0], al[1], al[2], al[3], bh[nt*2], bh[nt*2+1]);
                        mma_bf16(acc0[nt][0], acc0[nt][1], acc0[nt][2], acc0[nt][3],
                                 ah[0], ah[1], ah[2], ah[3], bl[nt*2], bl[nt*2+1]);
                    }
                }
            }
        }
    }
    __syncthreads();
    {
        float* dst = (float*)(smc + O_AHI);
        int pr = wid * 16 + (ln >> 2);
        int pc = (ln & 3) * 2;
        #pragma unroll
        for (int nt = 0; nt < 3; nt++) {
            dst[pr * 24 + nt * 8 + pc]           = acc0[nt][0];
            dst[pr * 24 + nt * 8 + pc + 1]       = acc0[nt][1];
            dst[(pr + 8) * 24 + nt * 8 + pc]     = acc0[nt][2];
            dst[(pr + 8) * 24 + nt * 8 + pc + 1] = acc0[nt][3];
        }
    }
    __syncthreads();
    {
        const float* dsm = (const float*)(smc + O_AHI);
        size_t mb = ((size_t)b * NPIX + p0) * 9;
        for (int i = t; i < 1152; i += 256) {
            int lp = i / 9, n = i - lp * 9;
            int pix = p0 + lp, hh = pix / 96, ww = pix - hh * 96;
            float ox = dsm[lp * 24 + n]     + __ldg(bof + n);
            float oy = dsm[lp * 24 + 9 + n] + __ldg(bof + 9 + n);
            float px = (float)(hh + n / 3 - 1) + ox;
            float py = (float)(ww + n % 3 - 1) + oy;
            px = fminf(fmaxf(px, -10000.f), 10000.f);
            py = fminf(fmaxf(py, -10000.f), 10000.f);
            float fx = floorf(px), fy = floorf(py);
            int x0 = (int)fx, y0 = (int)fy;
            g_mxy[mb + i]  = (x0 << 16) | (y0 & 0xffff);
            g_mlxy[mb + i] = make_float2(px - fx, py - fy);
        }
    }
}

// ================= K_MAIN: sampled main conv only =================
// smem: A_HI 16K, A_LO 16K, B_HI 8K, B_LO 8K  = 48K -> 2 CTAs/SM, large L1
#define M_AHI 0
#define M_ALO 16384
#define M_BHI 32768
#define M_BLO 40960
#define SMEM_MAIN 49152

__device__ __forceinline__ void sample_pix(const float* __restrict__ xb,
                                           size_t mb, int lp, int n, int l8,
                                           u32 aHiB, u32 aLoB) {
    size_t mi = mb + (size_t)lp * 9 + n;
    int xy = __ldg(g_mxy + mi);
    float2 l = __ldg(g_mlxy + mi);
    int x0 = xy >> 16, y0 = (xy << 16) >> 16;
    int x1 = x0 + 1, y1 = y0 + 1;
    float lx = l.x, ly = l.y;
    float w00 = (1.f - lx) * (1.f - ly);
    float w10 = lx * (1.f - ly);
    float w01 = (1.f - lx) * ly;
    float w11 = lx * ly;
    if ((unsigned)x0 >= 96u) { w00 = 0.f; w01 = 0.f; }
    if ((unsigned)x1 >= 96u) { w10 = 0.f; w11 = 0.f; }
    if ((unsigned)y0 >= 96u) { w00 = 0.f; w10 = 0.f; }
    if ((unsigned)y1 >= 96u) { w01 = 0.f; w11 = 0.f; }
    int cx0 = min(max(x0, 0), 95), cx1 = min(max(x1, 0), 95);
    int cy0 = min(max(y0, 0), 95), cy1 = min(max(y1, 0), 95);
    const float* pA = xb + (cx0 * 96 + cy0) * 64 + l8 * 8;
    const float* pB = xb + (cx1 * 96 + cy0) * 64 + l8 * 8;
    const float* pC = xb + (cx0 * 96 + cy1) * 64 + l8 * 8;
    const float* pD = xb + (cx1 * 96 + cy1) * 64 + l8 * 8;
    float4 A0 = *(const float4*)pA, A1 = *(const float4*)(pA + 4);
    float4 B0 = *(const float4*)pB, B1 = *(const float4*)(pB + 4);
    float4 C0 = *(const float4*)pC, C1 = *(const float4*)(pC + 4);
    float4 D0 = *(const float4*)pD, D1 = *(const float4*)(pD + 4);
    ull W00 = pack2(w00, w00), W10 = pack2(w10, w10);
    ull W01 = pack2(w01, w01), W11 = pack2(w11, w11);
    ull r0 = mul2(pack2(A0.x, A0.y), W00);
    ull r1 = mul2(pack2(A0.z, A0.w), W00);
    ull r2 = mul2(pack2(A1.x, A1.y), W00);
    ull r3 = mul2(pack2(A1.z, A1.w), W00);
    fma2(r0, pack2(B0.x, B0.y), W10); fma2(r1, pack2(B0.z, B0.w), W10);
    fma2(r2, pack2(B1.x, B1.y), W10); fma2(r3, pack2(B1.z, B1.w), W10);
    fma2(r0, pack2(C0.x, C0.y), W01); fma2(r1, pack2(C0.z, C0.w), W01);
    fma2(r2, pack2(C1.x, C1.y), W01); fma2(r3, pack2(C1.z, C1.w), W01);
    fma2(r0, pack2(D0.x, D0.y), W11); fma2(r1, pack2(D0.z, D0.w), W11);
    fma2(r2, pack2(D1.x, D1.y), W11); fma2(r3, pack2(D1.z, D1.w), W11);
    float s0, s1, s2, s3, s4, s5, s6, s7;
    unpack2(r0, s0, s1); unpack2(r1, s2, s3);
    unpack2(r2, s4, s5); unpack2(r3, s6, s7);
    u32 sa = swz((u32)(lp * 128 + l8 * 16));
    sts128(aHiB + sa, bfhi2(s0, s1), bfhi2(s2, s3), bfhi2(s4, s5), bfhi2(s6, s7));
    sts128(aLoB + sa, bflo2(s0, s1), bflo2(s2, s3), bflo2(s4, s5), bflo2(s6, s7));
}

__global__ __launch_bounds__(256, 2) void k_main(const float* __restrict__ bker,
                                                 float* __restrict__ out) {
    extern __shared__ char smc[];
    u32 sb = s2u(smc);
    int t = threadIdx.x, wid = t >> 5, ln = t & 31;
    int b = blockIdx.y;
    int p0 = blockIdx.x * 128;
    const float* xb = g_xt + (size_t)b * NPIX * 64;
    size_t mb = ((size_t)b * NPIX + p0) * 9;
    int l8 = ln & 7, g4 = ln >> 3;

    float acc[2][4][4];
    #pragma unroll
    for (int mt = 0; mt < 2; mt++)
        #pragma unroll
        for (int nt = 0; nt < 4; nt++)
            #pragma unroll
            for (int j = 0; j < 4; j++) acc[mt][nt][j] = 0.f;

    int mbase = (wid & 3) * 32, nbase = (wid >> 2) * 32;
    u32 arow = (u32)((mbase + (ln & 15)) * 128 + ((ln >> 4) * 16));
    u32 brow = (u32)((nbase + ((ln >> 4) << 3) + (ln & 7)) * 128 + (((ln >> 3) & 1) * 16));
    u32 aHiB = sb + M_AHI, aLoB = sb + M_ALO;
    u32 bHiB = sb + M_BHI, bLoB = sb + M_BLO;

    for (int n = 0; n < 9; n++) {
        if (n) __syncthreads();
        {
            const uint4* sh = (const uint4*)g_wbhi + n * 512;
            const uint4* sl = (const uint4*)g_wblo + n * 512;
            ((uint4*)(smc + M_BHI))[t]       = sh[t];
            ((uint4*)(smc + M_BHI))[t + 256] = sh[t + 256];
            ((uint4*)(smc + M_BLO))[t]       = sl[t];
            ((uint4*)(smc + M_BLO))[t + 256] = sl[t + 256];
        }
        #pragma unroll
        for (int i = 0; i < 4; i++) {
            int lp = wid * 16 + i * 4 + g4;
            sample_pix(xb, mb, lp, n, l8, aHiB, aLoB);
        }
        __syncthreads();
        #pragma unroll
        for (int k = 0; k < 4; k++) {
            u32 ka = (u32)(k * 32);
            u32 ah[8], al[8], bh[8], bl[8];
            ldsm4(aHiB + swz(arow + ka),        ah[0], ah[1], ah[2], ah[3]);
            ldsm4(aHiB + swz(arow + 2048 + ka), ah[4], ah[5], ah[6], ah[7]);
            ldsm4(aLoB + swz(arow + ka),        al[0], al[1], al[2], al[3]);
            ldsm4(aLoB + swz(arow + 2048 + ka), al[4], al[5], al[6], al[7]);
            ldsm4(bHiB + swz(brow + ka),        bh[0], bh[1], bh[2], bh[3]);
            ldsm4(bHiB + swz(brow + 2048 + ka), bh[4], bh[5], bh[6], bh[7]);
            ldsm4(bLoB + swz(brow + ka),        bl[0], bl[1], bl[2], bl[3]);
            ldsm4(bLoB + swz(brow + 2048 + ka), bl[4], bl[5], bl[6], bl[7]);
            #pragma unroll
            for (int mt = 0; mt < 2; mt++) {
                #pragma unroll
                for (int nt = 0; nt < 4; nt++) {
                    mma_bf16(acc[mt][nt][0], acc[mt][nt][1], acc[mt][nt][2], acc[mt][nt][3],
                             ah[mt*4], ah[mt*4+1], ah[mt*4+2], ah[mt*4+3], bh[nt*2], bh[nt*2+1]);
                    mma_bf16(acc[mt][nt][0], acc[mt][nt][1], acc[mt][nt][2], acc[mt][nt][3],
                             al[mt*4], al[mt*4+1], al[mt*4+2], al[mt*4+3], bh[nt*2], bh[nt*2+1]);
                    mma_bf16(acc[mt][nt][0], acc[mt][nt][1], acc[mt][nt][2], acc[mt][nt][3],
                             ah[mt*4], ah[mt*4+1], ah[mt*4+2], ah[mt*4+3], bl[nt*2], bl[nt*2+1]);
                }
            }
        }
    }

    // epilogue
    #pragma unroll
    for (int mt = 0; mt < 2; mt++) {
        #pragma unroll
        for (int nt = 0; nt < 4; nt++) {
            int pix = p0 + mbase + mt * 16 + (ln >> 2);
            int oc  = nbase + nt * 8 + (ln & 3) * 2;
            float b0 = __ldg(bker + oc), b1 = __ldg(bker + oc + 1);
            size_t base = ((size_t)(b * 64 + oc)) * NPIX + pix;
            out[base]            = acc[mt][nt][0] + b0;
            out[base + NPIX]     = acc[mt][nt][1] + b1;
            out[base + 8]        = acc[mt][nt][2] + b0;
            out[base + NPIX + 8] = acc[mt][nt][3] + b1;
        }
    }
}

// ================= launch =================
extern "C" void kernel_launch(void* const* d_in, const int* in_sizes, int n_in,
                              void* d_out, int out_size) {
    const float* x     = (const float*)d_in[0];
    const float* w_off = (const float*)d_in[1];
    const float* b_off = (const float*)d_in[2];
    const float* w_ker = (const float*)d_in[3];
    const float* b_ker = (const float*)d_in[4];
    float* out = (float*)d_out;

    cudaFuncSetAttribute(k_off,  cudaFuncAttributeMaxDynamicSharedMemorySize, SMEM_OFFK);
    cudaFuncSetAttribute(k_main, cudaFuncAttributeMaxDynamicSharedMemorySize, SMEM_MAIN);

    k_aux <<<dim3(144 + 27, BB), 256>>>(x, w_ker, w_off);
    k_off <<<dim3(NPIX / 128, BB), 256, SMEM_OFFK>>>(b_off);
    k_main<<<dim3(NPIX / 128, BB), 256, SMEM_MAIN>>>(b_ker, out);
}

// round 11
// speedup vs baseline: 1.2496x; 1.0692x over previous
#include <cuda_runtime.h>
#include <cuda_bf16.h>

// ---------------- constants ----------------
#define HH 96
#define WW 96
#define NPIX 9216
#define BB 8

typedef unsigned int u32;
typedef unsigned long long ull;

// ---------------- scratch ----------------
__device__ float g_xt[BB * NPIX * 64];            // x channels-last f32
__device__ unsigned short g_wbhi[9 * 64 * 64];    // main-conv B bf16 hi, swizzled [n][oc][ch]
__device__ unsigned short g_wblo[9 * 64 * 64];
__device__ unsigned short g_wobhi[9 * 32 * 64];   // offset-conv B (24 rows used, padded 32)
__device__ unsigned short g_woblo[9 * 32 * 64];

// ---------------- helpers ----------------
__device__ __forceinline__ u32 s2u(const void* p) {
    u32 a; asm("{ .reg .u64 t; cvta.to.shared.u64 t, %1; cvt.u32.u64 %0, t; }" : "=r"(a) : "l"(p));
    return a;
}
__device__ __forceinline__ u32 swz(u32 b) { return b ^ ((b >> 3) & 0x70); }

__device__ __forceinline__ void ldsm4(u32 a, u32& r0, u32& r1, u32& r2, u32& r3) {
    asm volatile("ldmatrix.sync.aligned.m8n8.x4.shared.b16 {%0,%1,%2,%3}, [%4];"
                 : "=r"(r0), "=r"(r1), "=r"(r2), "=r"(r3) : "r"(a));
}
__device__ __forceinline__ void mma_bf16(float& d0, float& d1, float& d2, float& d3,
                                         u32 a0, u32 a1, u32 a2, u32 a3, u32 b0, u32 b1) {
    asm volatile("mma.sync.aligned.m16n8k16.row.col.f32.bf16.bf16.f32 "
                 "{%0,%1,%2,%3},{%4,%5,%6,%7},{%8,%9},{%0,%1,%2,%3};"
                 : "+f"(d0), "+f"(d1), "+f"(d2), "+f"(d3)
                 : "r"(a0), "r"(a1), "r"(a2), "r"(a3), "r"(b0), "r"(b1));
}
__device__ __forceinline__ void sts128(u32 a, u32 x, u32 y, u32 z, u32 w) {
    asm volatile("st.shared.v4.b32 [%0],{%1,%2,%3,%4};" :: "r"(a), "r"(x), "r"(y), "r"(z), "r"(w) : "memory");
}
__device__ __forceinline__ void sts64(u32 a, u32 x, u32 y) {
    asm volatile("st.shared.v2.b32 [%0],{%1,%2};" :: "r"(a), "r"(x), "r"(y) : "memory");
}
__device__ __forceinline__ u32 bfhi2(float a, float b) {
    return __byte_perm(__float_as_uint(a), __float_as_uint(b), 0x7632);
}
__device__ __forceinline__ u32 bflo2(float a, float b) {
    float la = a - __uint_as_float(__float_as_uint(a) & 0xFFFF0000u);
    float lb = b - __uint_as_float(__float_as_uint(b) & 0xFFFF0000u);
    u32 r; asm("cvt.rn.bf16x2.f32 %0, %1, %2;" : "=r"(r) : "f"(lb), "f"(la));
    return r;
}
__device__ __forceinline__ ull pack2(float lo, float hi) {
    ull r; asm("mov.b64 %0, {%1,%2};" : "=l"(r) : "f"(lo), "f"(hi)); return r;
}
__device__ __forceinline__ void unpack2(ull v, float& lo, float& hi) {
    asm("mov.b64 {%0,%1}, %2;" : "=f"(lo), "=f"(hi) : "l"(v));
}
__device__ __forceinline__ ull mul2(ull a, ull b) {
    ull r; asm("mul.rn.f32x2 %0, %1, %2;" : "=l"(r) : "l"(a), "l"(b)); return r;
}
__device__ __forceinline__ void fma2(ull& d, ull a, ull b) {
    asm("fma.rn.f32x2 %0, %1, %2, %0;" : "+l"(d) : "l"(a), "l"(b));
}

// ================= K1: transpose x (b,c,h,w) -> (b,hw,c) =================
__global__ __launch_bounds__(256) void k_transpose(const float* __restrict__ x) {
    __shared__ float tile[64][65];
    int b  = blockIdx.y;
    int p0 = blockIdx.x << 6;
    int t  = threadIdx.x;
    #pragma unroll
    for (int i = t; i < 4096; i += 256) {
        int c = i >> 6, p = i & 63;
        tile[c][p] = x[((size_t)(b * 64 + c)) * NPIX + p0 + p];
    }
    __syncthreads();
    #pragma unroll
    for (int i = t; i < 4096; i += 256) {
        int p = i >> 6, c = i & 63;
        g_xt[((size_t)b * NPIX + p0 + p) * 64 + c] = tile[c][p];
    }
}

// ================= K0: weight prep =================
__global__ __launch_bounds__(256) void k_prep(const float* __restrict__ wker,
                                              const float* __restrict__ wof) {
    int i = blockIdx.x * 256 + threadIdx.x;
    if (i < 9 * 4096) {
        int n = i >> 12, r = i & 4095, oc = r >> 6, ch = r & 63;
        float v = wker[(oc * 64 + ch) * 9 + n];
        u32 hib = __float_as_uint(v) & 0xFFFF0000u;
        float lv = v - __uint_as_float(hib);
        __nv_bfloat16 lb = __float2bfloat16(lv);
        u32 sw = swz((u32)(oc * 128 + ch * 2)) >> 1;
        g_wbhi[n * 4096 + sw] = (unsigned short)(hib >> 16);
        g_wblo[n * 4096 + sw] = *(unsigned short*)&lb;
    } else {
        int j = i - 9 * 4096;
        if (j < 9 * 2048) {
            int n = j >> 11, r = j & 2047, oc = r >> 6, ch = r & 63;
            float v = (oc < 18) ? wof[(oc * 64 + ch) * 9 + n] : 0.f;
            u32 hib = __float_as_uint(v) & 0xFFFF0000u;
            float lv = v - __uint_as_float(hib);
            __nv_bfloat16 lb = __float2bfloat16(lv);
            u32 sw = swz((u32)(oc * 128 + ch * 2)) >> 1;
            g_wobhi[n * 2048 + sw] = (unsigned short)(hib >> 16);
            g_woblo[n * 2048 + sw] = *(unsigned short*)&lb;
        }
    }
}

// ================= K_MAIN =================
#define A_HI    0
#define A_LO    16384
#define B_HI    32768
#define B_LO    40960
#define OFF_MO  49152
#define OFF_MW  67584
#define SMEM_MAIN 86016

__global__ __launch_bounds__(256, 2) void k_main(const float* __restrict__ bof,
                                                 const float* __restrict__ bker,
                                                 float* __restrict__ out) {
    extern __shared__ char smc[];
    u32 sb = s2u(smc);
    int t = threadIdx.x, wid = t >> 5, ln = t & 31;
    int b = blockIdx.y;
    int p0 = blockIdx.x * 128;
    const float* xb = g_xt + (size_t)b * NPIX * 64;
    u32 aHiB = sb + A_HI, aLoB = sb + A_LO, bHiB = sb + B_HI, bLoB = sb + B_LO;

    // ========== PHASE 0: offset conv (3-term hi/lo split), all 8 warps ==========
    float acc0[3][4];
    #pragma unroll
    for (int nt = 0; nt < 3; nt++)
        #pragma unroll
        for (int j = 0; j < 4; j++) acc0[nt][j] = 0.f;

    {
        int lp = t >> 1, q = t & 1;
        int pix = p0 + lp, hh = pix / 96, ww = pix - hh * 96;

        for (int tap = 0; tap < 9; tap++) {
            __syncthreads();
            ((uint4*)(smc + B_HI))[t] = ((const uint4*)g_wobhi + tap * 256)[t];
            ((uint4*)(smc + B_LO))[t] = ((const uint4*)g_woblo + tap * 256)[t];
            // A-build (hi + lo residual) from f32 channels-last
            {
                int sh_ = hh + tap / 3 - 1, sw_ = ww + tap % 3 - 1;
                bool ok = ((unsigned)sh_ < 96u) & ((unsigned)sw_ < 96u);
                float4 v[8];
                if (ok) {
                    const float4* src = (const float4*)(xb + (size_t)(sh_ * 96 + sw_) * 64) + q * 8;
                    #pragma unroll
                    for (int j = 0; j < 8; j++) v[j] = src[j];
                } else {
                    #pragma unroll
                    for (int j = 0; j < 8; j++) v[j] = make_float4(0.f, 0.f, 0.f, 0.f);
                }
                u32 rowb = (u32)(lp * 128 + q * 64);
                #pragma unroll
                for (int j = 0; j < 4; j++) {
                    u32 sa = swz(rowb + j * 16);
                    sts128(aHiB + sa, bfhi2(v[2*j].x, v[2*j].y), bfhi2(v[2*j].z, v[2*j].w),
                                      bfhi2(v[2*j+1].x, v[2*j+1].y), bfhi2(v[2*j+1].z, v[2*j+1].w));
                    sts128(aLoB + sa, bflo2(v[2*j].x, v[2*j].y), bflo2(v[2*j].z, v[2*j].w),
                                      bflo2(v[2*j+1].x, v[2*j+1].y), bflo2(v[2*j+1].z, v[2*j+1].w));
                }
            }
            __syncthreads();
            {
                u32 arow = (u32)((wid * 16 + (ln & 15)) * 128 + ((ln >> 4) * 16));
                u32 brow = (u32)(((((ln >> 4) << 3) + (ln & 7))) * 128 + (((ln >> 3) & 1) * 16));
                #pragma unroll
                for (int k = 0; k < 4; k++) {
                    u32 ka = (u32)(k * 32);
                    u32 ah[4], al[4], bh[8], bl[8];
                    ldsm4(aHiB + swz(arow + ka), ah[0], ah[1], ah[2], ah[3]);
                    ldsm4(aLoB + swz(arow + ka), al[0], al[1], al[2], al[3]);
                    ldsm4(bHiB + swz(brow + ka), bh[0], bh[1], bh[2], bh[3]);
                    ldsm4(bHiB + swz(brow + 2048 + ka), bh[4], bh[5], bh[6], bh[7]);
                    ldsm4(bLoB + swz(brow + ka), bl[0], bl[1], bl[2], bl[3]);
                    ldsm4(bLoB + swz(brow + 2048 + ka), bl[4], bl[5], bl[6], bl[7]);
                    #pragma unroll
                    for (int nt = 0; nt < 3; nt++) {
                        mma_bf16(acc0[nt][0], acc0[nt][1], acc0[nt][2], acc0[nt][3],
                                 ah[0], ah[1], ah[2], ah[3], bh[nt*2], bh[nt*2+1]);
                        mma_bf16(acc0[nt][0], acc0[nt][1], acc0[nt][2], acc0[nt][3],
                                 al[0], al[1], al[2], al[3], bh[nt*2], bh[nt*2+1]);
                        mma_bf16(acc0[nt][0], acc0[nt][1], acc0[nt][2], acc0[nt][3],
                                 ah[0], ah[1], ah[2], ah[3], bl[nt*2], bl[nt*2+1]);
                    }
                }
            }
        }
    }
    __syncthreads();
    {
        float* dst = (float*)(smc + A_HI);
        int pr = wid * 16 + (ln >> 2);
        int pc = (ln & 3) * 2;
        #pragma unroll
        for (int nt = 0; nt < 3; nt++) {
            dst[pr * 24 + nt * 8 + pc]           = acc0[nt][0];
            dst[pr * 24 + nt * 8 + pc + 1]       = acc0[nt][1];
            dst[(pr + 8) * 24 + nt * 8 + pc]     = acc0[nt][2];
            dst[(pr + 8) * 24 + nt * 8 + pc + 1] = acc0[nt][3];
        }
    }
    __syncthreads();
    {
        const float* dsm = (const float*)(smc + A_HI);
        int4*   mo = (int4*)(smc + OFF_MO);
        float4* mw = (float4*)(smc + OFF_MW);
        for (int i = t; i < 1152; i += 256) {
            int lp = i / 9, n = i - lp * 9;
            int pix = p0 + lp, hh = pix / 96, ww = pix - hh * 96;
            float ox = dsm[lp * 24 + n]     + __ldg(bof + n);
            float oy = dsm[lp * 24 + 9 + n] + __ldg(bof + 9 + n);
            float px = (float)(hh + n / 3 - 1) + ox;
            float py = (float)(ww + n % 3 - 1) + oy;
            px = fminf(fmaxf(px, -10000.f), 10000.f);
            py = fminf(fmaxf(py, -10000.f), 10000.f);
            float fx = floorf(px), fy = floorf(py);
            float lx = px - fx, ly = py - fy;
            int x0 = (int)fx, y0 = (int)fy, x1 = x0 + 1, y1 = y0 + 1;
            float w00 = (1.f - lx) * (1.f - ly);
            float w10 = lx * (1.f - ly);
            float w01 = (1.f - lx) * ly;
            float w11 = lx * ly;
            if ((unsigned)x0 >= 96u) { w00 = 0.f; w01 = 0.f; }
            if ((unsigned)x1 >= 96u) { w10 = 0.f; w11 = 0.f; }
            if ((unsigned)y0 >= 96u) { w00 = 0.f; w10 = 0.f; }
            if ((unsigned)y1 >= 96u) { w01 = 0.f; w11 = 0.f; }
            int cx0 = min(max(x0, 0), 95), cx1 = min(max(x1, 0), 95);
            int cy0 = min(max(y0, 0), 95), cy1 = min(max(y1, 0), 95);
            mo[i] = make_int4((cx0 * 96 + cy0) * 64, (cx1 * 96 + cy0) * 64,
                              (cx0 * 96 + cy1) * 64, (cx1 * 96 + cy1) * 64);
            mw[i] = make_float4(w00, w10, w01, w11);
        }
    }

    // ================= PHASE 1: sampled main conv =================
    float acc[2][4][4];
    #pragma unroll
    for (int mt = 0; mt < 2; mt++)
        #pragma unroll
        for (int nt = 0; nt < 4; nt++)
            #pragma unroll
            for (int j = 0; j < 4; j++) acc[mt][nt][j] = 0.f;

    int l8 = ln & 7, g4 = ln >> 3;     // lane -> (pixel-in-group g4, 4-ch slice l8)
    const int4*   mo = (const int4*)(smc + OFF_MO);
    const float4* mw = (const float4*)(smc + OFF_MW);

    for (int n = 0; n < 9; n++) {
        __syncthreads();
        {
            const uint4* sh = (const uint4*)g_wbhi + n * 512;
            const uint4* sl = (const uint4*)g_wblo + n * 512;
            uint4* dh = (uint4*)(smc + B_HI);
            uint4* dl = (uint4*)(smc + B_LO);
            dh[t] = sh[t]; dh[t + 256] = sh[t + 256];
            dl[t] = sl[t]; dl[t + 256] = sl[t + 256];
        }
        // sample: warp = 4 pixels x 8 lanes; lane l8 owns channels [l8*4,+4) and [32+l8*4,+4)
        // -> each warp-LDG touches exactly 1 line per pixel (A0 = line 0, A1 = line 1)
        #pragma unroll
        for (int i = 0; i < 4; i++) {
            int lp = wid * 16 + i * 4 + g4;
            int mi = lp * 9 + n;
            int4   o4 = mo[mi];
            float4 w4 = mw[mi];
            const float* pA = xb + o4.x + l8 * 4;
            const float* pB = xb + o4.y + l8 * 4;
            const float* pC = xb + o4.z + l8 * 4;
            const float* pD = xb + o4.w + l8 * 4;
            float4 A0 = *(const float4*)pA, A1 = *(const float4*)(pA + 32);
            float4 B0 = *(const float4*)pB, B1 = *(const float4*)(pB + 32);
            float4 C0 = *(const float4*)pC, C1 = *(const float4*)(pC + 32);
            float4 D0 = *(const float4*)pD, D1 = *(const float4*)(pD + 32);
            ull W00 = pack2(w4.x, w4.x), W10 = pack2(w4.y, w4.y);
            ull W01 = pack2(w4.z, w4.z), W11 = pack2(w4.w, w4.w);
            ull r0 = mul2(pack2(A0.x, A0.y), W00);
            ull r1 = mul2(pack2(A0.z, A0.w), W00);
            ull r2 = mul2(pack2(A1.x, A1.y), W00);
            ull r3 = mul2(pack2(A1.z, A1.w), W00);
            fma2(r0, pack2(B0.x, B0.y), W10); fma2(r1, pack2(B0.z, B0.w), W10);
            fma2(r2, pack2(B1.x, B1.y), W10); fma2(r3, pack2(B1.z, B1.w), W10);
            fma2(r0, pack2(C0.x, C0.y), W01); fma2(r1, pack2(C0.z, C0.w), W01);
            fma2(r2, pack2(C1.x, C1.y), W01); fma2(r3, pack2(C1.z, C1.w), W01);
            fma2(r0, pack2(D0.x, D0.y), W11); fma2(r1, pack2(D0.z, D0.w), W11);
            fma2(r2, pack2(D1.x, D1.y), W11); fma2(r3, pack2(D1.z, D1.w), W11);
            float s0, s1, s2, s3, s4, s5, s6, s7;
            unpack2(r0, s0, s1); unpack2(r1, s2, s3);
            unpack2(r2, s4, s5); unpack2(r3, s6, s7);
            u32 sa0 = swz((u32)(lp * 128 + l8 * 8));
            u32 sa1 = swz((u32)(lp * 128 + 64 + l8 * 8));
            sts64(aHiB + sa0, bfhi2(s0, s1), bfhi2(s2, s3));
            sts64(aHiB + sa1, bfhi2(s4, s5), bfhi2(s6, s7));
            sts64(aLoB + sa0, bflo2(s0, s1), bflo2(s2, s3));
            sts64(aLoB + sa1, bflo2(s4, s5), bflo2(s6, s7));
        }
        __syncthreads();
        {
            int mbase = (wid & 3) * 32, nbase = (wid >> 2) * 32;
            u32 arow = (u32)((mbase + (ln & 15)) * 128 + ((ln >> 4) * 16));
            u32 brow = (u32)((nbase + ((ln >> 4) << 3) + (ln & 7)) * 128 + (((ln >> 3) & 1) * 16));
            #pragma unroll
            for (int k = 0; k < 4; k++) {
                u32 ka = (u32)(k * 32);
                u32 ah[8], al[8], bh[8], bl[8];
                ldsm4(aHiB + swz(arow + ka),        ah[0], ah[1], ah[2], ah[3]);
                ldsm4(aHiB + swz(arow + 2048 + ka), ah[4], ah[5], ah[6], ah[7]);
                ldsm4(aLoB + swz(arow + ka),        al[0], al[1], al[2], al[3]);
                ldsm4(aLoB + swz(arow + 2048 + ka), al[4], al[5], al[6], al[7]);
                ldsm4(bHiB + swz(brow + ka),        bh[0], bh[1], bh[2], bh[3]);
                ldsm4(bHiB + swz(brow + 2048 + ka), bh[4], bh[5], bh[6], bh[7]);
                ldsm4(bLoB + swz(brow + ka),        bl[0], bl[1], bl[2], bl[3]);
                ldsm4(bLoB + swz(brow + 2048 + ka), bl[4], bl[5], bl[6], bl[7]);
                #pragma unroll
                for (int mt = 0; mt < 2; mt++) {
                    #pragma unroll
                    for (int nt = 0; nt < 4; nt++) {
                        mma_bf16(acc[mt][nt][0], acc[mt][nt][1], acc[mt][nt][2], acc[mt][nt][3],
                                 ah[mt*4], ah[mt*4+1], ah[mt*4+2], ah[mt*4+3], bh[nt*2], bh[nt*2+1]);
                        mma_bf16(acc[mt][nt][0], acc[mt][nt][1], acc[mt][nt][2], acc[mt][nt][3],
                                 al[mt*4], al[mt*4+1], al[mt*4+2], al[mt*4+3], bh[nt*2], bh[nt*2+1]);
                        mma_bf16(acc[mt][nt][0], acc[mt][nt][1], acc[mt][nt][2], acc[mt][nt][3],
                                 ah[mt*4], ah[mt*4+1], ah[mt*4+2], ah[mt*4+3], bl[nt*2], bl[nt*2+1]);
                    }
                }
            }
        }
    }

    // ================= epilogue =================
    {
        int mbase = (wid & 3) * 32, nbase = (wid >> 2) * 32;
        #pragma unroll
        for (int mt = 0; mt < 2; mt++) {
            #pragma unroll
            for (int nt = 0; nt < 4; nt++) {
                int pix = p0 + mbase + mt * 16 + (ln >> 2);
                int oc  = nbase + nt * 8 + (ln & 3) * 2;
                float b0 = __ldg(bker + oc), b1 = __ldg(bker + oc + 1);
                size_t base = ((size_t)(b * 64 + oc)) * NPIX + pix;
                out[base]            = acc[mt][nt][0] + b0;
                out[base + NPIX]     = acc[mt][nt][1] + b1;
                out[base + 8]        = acc[mt][nt][2] + b0;
                out[base + NPIX + 8] = acc[mt][nt][3] + b1;
            }
        }
    }
}

// ================= launch =================
extern "C" void kernel_launch(void* const* d_in, const int* in_sizes, int n_in,
                              void* d_out, int out_size) {
    const float* x     = (const float*)d_in[0];
    const float* w_off = (const float*)d_in[1];
    const float* b_off = (const float*)d_in[2];
    const float* w_ker = (const float*)d_in[3];
    const float* b_ker = (const float*)d_in[4];
    float* out = (float*)d_out;

    cudaFuncSetAttribute(k_main, cudaFuncAttributeMaxDynamicSharedMemorySize, SMEM_MAIN);

    k_transpose<<<dim3(NPIX / 64, BB), 256>>>(x);
    k_prep<<<(9 * 4096 + 9 * 2048 + 255) / 256, 256>>>(w_ker, w_off);
    k_main<<<dim3(NPIX / 128, BB), 256, SMEM_MAIN>>>(b_off, b_ker, out);
}

// round 14
// speedup vs baseline: 1.4691x; 1.1757x over previous
#include <cuda_runtime.h>
#include <cuda_bf16.h>
#include <cuda_fp16.h>

// ---------------- constants ----------------
#define HH 96
#define WW 96
#define NPIX 9216
#define BB 8

typedef unsigned int u32;
typedef unsigned long long ull;

// ---------------- scratch ----------------
__device__ float g_xt[BB * NPIX * 64];            // x channels-last f32
__device__ unsigned short g_wf[9 * 64 * 64];      // main-conv B fp16 (RN), swizzled [n][oc][ch]
__device__ unsigned short g_wobhi[9 * 32 * 64];   // offset-conv B bf16 hi (24 rows used, padded 32)
__device__ unsigned short g_woblo[9 * 32 * 64];   // offset-conv B bf16 lo

// ---------------- helpers ----------------
__device__ __forceinline__ u32 s2u(const void* p) {
    u32 a; asm("{ .reg .u64 t; cvta.to.shared.u64 t, %1; cvt.u32.u64 %0, t; }" : "=r"(a) : "l"(p));
    return a;
}
__device__ __forceinline__ u32 swz(u32 b) { return b ^ ((b >> 3) & 0x70); }

__device__ __forceinline__ void ldsm4(u32 a, u32& r0, u32& r1, u32& r2, u32& r3) {
    asm volatile("ldmatrix.sync.aligned.m8n8.x4.shared.b16 {%0,%1,%2,%3}, [%4];"
                 : "=r"(r0), "=r"(r1), "=r"(r2), "=r"(r3) : "r"(a));
}
__device__ __forceinline__ void mma_bf16(float& d0, float& d1, float& d2, float& d3,
                                         u32 a0, u32 a1, u32 a2, u32 a3, u32 b0, u32 b1) {
    asm volatile("mma.sync.aligned.m16n8k16.row.col.f32.bf16.bf16.f32 "
                 "{%0,%1,%2,%3},{%4,%5,%6,%7},{%8,%9},{%0,%1,%2,%3};"
                 : "+f"(d0), "+f"(d1), "+f"(d2), "+f"(d3)
                 : "r"(a0), "r"(a1), "r"(a2), "r"(a3), "r"(b0), "r"(b1));
}
__device__ __forceinline__ void mma_f16(float& d0, float& d1, float& d2, float& d3,
                                        u32 a0, u32 a1, u32 a2, u32 a3, u32 b0, u32 b1) {
    asm volatile("mma.sync.aligned.m16n8k16.row.col.f32.f16.f16.f32 "
                 "{%0,%1,%2,%3},{%4,%5,%6,%7},{%8,%9},{%0,%1,%2,%3};"
                 : "+f"(d0), "+f"(d1), "+f"(d2), "+f"(d3)
                 : "r"(a0), "r"(a1), "r"(a2), "r"(a3), "r"(b0), "r"(b1));
}
__device__ __forceinline__ void sts128(u32 a, u32 x, u32 y, u32 z, u32 w) {
    asm volatile("st.shared.v4.b32 [%0],{%1,%2,%3,%4};" :: "r"(a), "r"(x), "r"(y), "r"(z), "r"(w) : "memory");
}
__device__ __forceinline__ void sts64(u32 a, u32 x, u32 y) {
    asm volatile("st.shared.v2.b32 [%0],{%1,%2};" :: "r"(a), "r"(x), "r"(y) : "memory");
}
__device__ __forceinline__ u32 bfhi2(float a, float b) {
    return __byte_perm(__float_as_uint(a), __float_as_uint(b), 0x7632);
}
__device__ __forceinline__ u32 bflo2(float a, float b) {
    float la = a - __uint_as_float(__float_as_uint(a) & 0xFFFF0000u);
    float lb = b - __uint_as_float(__float_as_uint(b) & 0xFFFF0000u);
    u32 r; asm("cvt.rn.bf16x2.f32 %0, %1, %2;" : "=r"(r) : "f"(lb), "f"(la));
    return r;
}
__device__ __forceinline__ u32 f16x2(float lo, float hi) {   // lo -> low half
    u32 r; asm("cvt.rn.f16x2.f32 %0, %1, %2;" : "=r"(r) : "f"(hi), "f"(lo));
    return r;
}
__device__ __forceinline__ ull pack2(float lo, float hi) {
    ull r; asm("mov.b64 %0, {%1,%2};" : "=l"(r) : "f"(lo), "f"(hi)); return r;
}
__device__ __forceinline__ void unpack2(ull v, float& lo, float& hi) {
    asm("mov.b64 {%0,%1}, %2;" : "=f"(lo), "=f"(hi) : "l"(v));
}
__device__ __forceinline__ ull mul2(ull a, ull b) {
    ull r; asm("mul.rn.f32x2 %0, %1, %2;" : "=l"(r) : "l"(a), "l"(b)); return r;
}
__device__ __forceinline__ void fma2(ull& d, ull a, ull b) {
    asm("fma.rn.f32x2 %0, %1, %2, %0;" : "+l"(d) : "l"(a), "l"(b));
}

// ================= K1: transpose x (b,c,h,w) -> (b,hw,c) =================
__global__ __launch_bounds__(256) void k_transpose(const float* __restrict__ x) {
    __shared__ float tile[64][65];
    int b  = blockIdx.y;
    int p0 = blockIdx.x << 6;
    int t  = threadIdx.x;
    #pragma unroll
    for (int i = t; i < 4096; i += 256) {
        int c = i >> 6, p = i & 63;
        tile[c][p] = x[((size_t)(b * 64 + c)) * NPIX + p0 + p];
    }
    __syncthreads();
    #pragma unroll
    for (int i = t; i < 4096; i += 256) {
        int p = i >> 6, c = i & 63;
        g_xt[((size_t)b * NPIX + p0 + p) * 64 + c] = tile[c][p];
    }
}

// ================= K0: weight prep =================
__global__ __launch_bounds__(256) void k_prep(const float* __restrict__ wker,
                                              const float* __restrict__ wof) {
    int i = blockIdx.x * 256 + threadIdx.x;
    if (i < 9 * 4096) {
        int n = i >> 12, r = i & 4095, oc = r >> 6, ch = r & 63;
        float v = wker[(oc * 64 + ch) * 9 + n];
        __half h = __float2half_rn(v);
        u32 sw = swz((u32)(oc * 128 + ch * 2)) >> 1;
        g_wf[n * 4096 + sw] = *(unsigned short*)&h;
    } else {
        int j = i - 9 * 4096;
        if (j < 9 * 2048) {
            int n = j >> 11, r = j & 2047, oc = r >> 6, ch = r & 63;
            float v = (oc < 18) ? wof[(oc * 64 + ch) * 9 + n] : 0.f;
            u32 hib = __float_as_uint(v) & 0xFFFF0000u;
            float lv = v - __uint_as_float(hib);
            __nv_bfloat16 lb = __float2bfloat16(lv);
            u32 sw = swz((u32)(oc * 128 + ch * 2)) >> 1;
            g_wobhi[n * 2048 + sw] = (unsigned short)(hib >> 16);
            g_woblo[n * 2048 + sw] = *(unsigned short*)&lb;
        }
    }
}

// ================= K_MAIN =================
#define A_HI    0
#define A_LO    16384
#define B_HI    32768
#define B_LO    40960
#define OFF_MO  49152
#define OFF_MW  67584
#define SMEM_MAIN 86016

__global__ __launch_bounds__(256, 2) void k_main(const float* __restrict__ bof,
                                                 const float* __restrict__ bker,
                                                 float* __restrict__ out) {
    extern __shared__ char smc[];
    u32 sb = s2u(smc);
    int t = threadIdx.x, wid = t >> 5, ln = t & 31;
    int b = blockIdx.y;
    int p0 = blockIdx.x * 128;
    const float* xb = g_xt + (size_t)b * NPIX * 64;
    u32 aHiB = sb + A_HI, aLoB = sb + A_LO, bHiB = sb + B_HI, bLoB = sb + B_LO;

    // ========== PHASE 0: offset conv (bf16 3-term hi/lo split), all 8 warps ==========
    float acc0[3][4];
    #pragma unroll
    for (int nt = 0; nt < 3; nt++)
        #pragma unroll
        for (int j = 0; j < 4; j++) acc0[nt][j] = 0.f;

    {
        int lp = t >> 1, q = t & 1;
        int pix = p0 + lp, hh = pix / 96, ww = pix - hh * 96;

        for (int tap = 0; tap < 9; tap++) {
            __syncthreads();
            ((uint4*)(smc + B_HI))[t] = ((const uint4*)g_wobhi + tap * 256)[t];
            ((uint4*)(smc + B_LO))[t] = ((const uint4*)g_woblo + tap * 256)[t];
            // A-build (hi + lo residual) from f32 channels-last
            {
                int sh_ = hh + tap / 3 - 1, sw_ = ww + tap % 3 - 1;
                bool ok = ((unsigned)sh_ < 96u) & ((unsigned)sw_ < 96u);
                float4 v[8];
                if (ok) {
                    const float4* src = (const float4*)(xb + (size_t)(sh_ * 96 + sw_) * 64) + q * 8;
                    #pragma unroll
                    for (int j = 0; j < 8; j++) v[j] = src[j];
                } else {
                    #pragma unroll
                    for (int j = 0; j < 8; j++) v[j] = make_float4(0.f, 0.f, 0.f, 0.f);
                }
                u32 rowb = (u32)(lp * 128 + q * 64);
                #pragma unroll
                for (int j = 0; j < 4; j++) {
                    u32 sa = swz(rowb + j * 16);
                    sts128(aHiB + sa, bfhi2(v[2*j].x, v[2*j].y), bfhi2(v[2*j].z, v[2*j].w),
                                      bfhi2(v[2*j+1].x, v[2*j+1].y), bfhi2(v[2*j+1].z, v[2*j+1].w));
                    sts128(aLoB + sa, bflo2(v[2*j].x, v[2*j].y), bflo2(v[2*j].z, v[2*j].w),
                                      bflo2(v[2*j+1].x, v[2*j+1].y), bflo2(v[2*j+1].z, v[2*j+1].w));
                }
            }
            __syncthreads();
            {
                u32 arow = (u32)((wid * 16 + (ln & 15)) * 128 + ((ln >> 4) * 16));
                u32 brow = (u32)(((((ln >> 4) << 3) + (ln & 7))) * 128 + (((ln >> 3) & 1) * 16));
                #pragma unroll
                for (int k = 0; k < 4; k++) {
                    u32 ka = (u32)(k * 32);
                    u32 ah[4], al[4], bh[8], bl[8];
                    ldsm4(aHiB + swz(arow + ka), ah[0], ah[1], ah[2], ah[3]);
                    ldsm4(aLoB + swz(arow + ka), al[0], al[1], al[2], al[3]);
                    ldsm4(bHiB + swz(brow + ka), bh[0], bh[1], bh[2], bh[3]);
                    ldsm4(bHiB + swz(brow + 2048 + ka), bh[4], bh[5], bh[6], bh[7]);
                    ldsm4(bLoB + swz(brow + ka), bl[0], bl[1], bl[2], bl[3]);
                    ldsm4(bLoB + swz(brow + 2048 + ka), bl[4], bl[5], bl[6], bl[7]);
                    #pragma unroll
                    for (int nt = 0; nt < 3; nt++) {
                        mma_bf16(acc0[nt][0], acc0[nt][1], acc0[nt][2], acc0[nt][3],
                                 ah[0], ah[1], ah[2], ah[3], bh[nt*2], bh[nt*2+1]);
                        mma_bf16(acc0[nt][0], acc0[nt][1], acc0[nt][2], acc0[nt][3],
                                 al[0], al[1], al[2], al[3], bh[nt*2], bh[nt*2+1]);
                        mma_bf16(acc0[nt][0], acc0[nt][1], acc0[nt][2], acc0[nt][3],
                                 ah[0], ah[1], ah[2], ah[3], bl[nt*2], bl[nt*2+1]);
                    }
                }
            }
        }
    }
    __syncthreads();
    {
        float* dst = (float*)(smc + A_HI);
        int pr = wid * 16 + (ln >> 2);
        int pc = (ln & 3) * 2;
        #pragma unroll
        for (int nt = 0; nt < 3; nt++) {
            dst[pr * 24 + nt * 8 + pc]           = acc0[nt][0];
            dst[pr * 24 + nt * 8 + pc + 1]       = acc0[nt][1];
            dst[(pr + 8) * 24 + nt * 8 + pc]     = acc0[nt][2];
            dst[(pr + 8) * 24 + nt * 8 + pc + 1] = acc0[nt][3];
        }
    }
    __syncthreads();
    {
        const float* dsm = (const float*)(smc + A_HI);
        int4*   mo = (int4*)(smc + OFF_MO);
        float4* mw = (float4*)(smc + OFF_MW);
        for (int i = t; i < 1152; i += 256) {
            int lp = i / 9, n = i - lp * 9;
            int pix = p0 + lp, hh = pix / 96, ww = pix - hh * 96;
            float ox = dsm[lp * 24 + n]     + __ldg(bof + n);
            float oy = dsm[lp * 24 + 9 + n] + __ldg(bof + 9 + n);
            float px = (float)(hh + n / 3 - 1) + ox;
            float py = (float)(ww + n % 3 - 1) + oy;
            px = fminf(fmaxf(px, -10000.f), 10000.f);
            py = fminf(fmaxf(py, -10000.f), 10000.f);
            float fx = floorf(px), fy = floorf(py);
            float lx = px - fx, ly = py - fy;
            int x0 = (int)fx, y0 = (int)fy, x1 = x0 + 1, y1 = y0 + 1;
            float w00 = (1.f - lx) * (1.f - ly);
            float w10 = lx * (1.f - ly);
            float w01 = (1.f - lx) * ly;
            float w11 = lx * ly;
            if ((unsigned)x0 >= 96u) { w00 = 0.f; w01 = 0.f; }
            if ((unsigned)x1 >= 96u) { w10 = 0.f; w11 = 0.f; }
            if ((unsigned)y0 >= 96u) { w00 = 0.f; w10 = 0.f; }
            if ((unsigned)y1 >= 96u) { w01 = 0.f; w11 = 0.f; }
            int cx0 = min(max(x0, 0), 95), cx1 = min(max(x1, 0), 95);
            int cy0 = min(max(y0, 0), 95), cy1 = min(max(y1, 0), 95);
            mo[i] = make_int4((cx0 * 96 + cy0) * 64, (cx1 * 96 + cy0) * 64,
                              (cx0 * 96 + cy1) * 64, (cx1 * 96 + cy1) * 64);
            mw[i] = make_float4(w00, w10, w01, w11);
        }
    }

    // ================= PHASE 1: sampled main conv (single-term fp16) =================
    float acc[2][4][4];
    #pragma unroll
    for (int mt = 0; mt < 2; mt++)
        #pragma unroll
        for (int nt = 0; nt < 4; nt++)
            #pragma unroll
            for (int j = 0; j < 4; j++) acc[mt][nt][j] = 0.f;

    int l8 = ln & 7, g4 = ln >> 3;     // lane -> (pixel-in-group g4, 4-ch slice l8)
    const int4*   mo = (const int4*)(smc + OFF_MO);
    const float4* mw = (const float4*)(smc + OFF_MW);

    for (int n = 0; n < 9; n++) {
        __syncthreads();
        {
            // stage fp16 weights for this n: 8KB
            const uint4* sw4 = (const uint4*)g_wf + n * 512;
            uint4* dh = (uint4*)(smc + B_HI);
            dh[t] = sw4[t]; dh[t + 256] = sw4[t + 256];
        }
        // sample: warp = 4 pixels x 8 lanes; lane l8 owns channels [l8*4,+4) and [32+l8*4,+4)
        #pragma unroll
        for (int i = 0; i < 4; i++) {
            int lp = wid * 16 + i * 4 + g4;
            int mi = lp * 9 + n;
            int4   o4 = mo[mi];
            float4 w4 = mw[mi];
            const float* pA = xb + o4.x + l8 * 4;
            const float* pB = xb + o4.y + l8 * 4;
            const float* pC = xb + o4.z + l8 * 4;
            const float* pD = xb + o4.w + l8 * 4;
            float4 A0 = *(const float4*)pA, A1 = *(const float4*)(pA + 32);
            float4 B0 = *(const float4*)pB, B1 = *(const float4*)(pB + 32);
            float4 C0 = *(const float4*)pC, C1 = *(const float4*)(pC + 32);
            float4 D0 = *(const float4*)pD, D1 = *(const float4*)(pD + 32);
            ull W00 = pack2(w4.x, w4.x), W10 = pack2(w4.y, w4.y);
            ull W01 = pack2(w4.z, w4.z), W11 = pack2(w4.w, w4.w);
            ull r0 = mul2(pack2(A0.x, A0.y), W00);
            ull r1 = mul2(pack2(A0.z, A0.w), W00);
            ull r2 = mul2(pack2(A1.x, A1.y), W00);
            ull r3 = mul2(pack2(A1.z, A1.w), W00);
            fma2(r0, pack2(B0.x, B0.y), W10); fma2(r1, pack2(B0.z, B0.w), W10);
            fma2(r2, pack2(B1.x, B1.y), W10); fma2(r3, pack2(B1.z, B1.w), W10);
            fma2(r0, pack2(C0.x, C0.y), W01); fma2(r1, pack2(C0.z, C0.w), W01);
            fma2(r2, pack2(C1.x, C1.y), W01); fma2(r3, pack2(C1.z, C1.w), W01);
            fma2(r0, pack2(D0.x, D0.y), W11); fma2(r1, pack2(D0.z, D0.w), W11);
            fma2(r2, pack2(D1.x, D1.y), W11); fma2(r3, pack2(D1.z, D1.w), W11);
            float s0, s1, s2, s3, s4, s5, s6, s7;
            unpack2(r0, s0, s1); unpack2(r1, s2, s3);
            unpack2(r2, s4, s5); unpack2(r3, s6, s7);
            u32 sa0 = swz((u32)(lp * 128 + l8 * 8));
            u32 sa1 = swz((u32)(lp * 128 + 64 + l8 * 8));
            sts64(aHiB + sa0, f16x2(s0, s1), f16x2(s2, s3));
            sts64(aHiB + sa1, f16x2(s4, s5), f16x2(s6, s7));
        }
        __syncthreads();
        {
            int mbase = (wid & 3) * 32, nbase = (wid >> 2) * 32;
            u32 arow = (u32)((mbase + (ln & 15)) * 128 + ((ln >> 4) * 16));
            u32 brow = (u32)((nbase + ((ln >> 4) << 3) + (ln & 7)) * 128 + (((ln >> 3) & 1) * 16));
            #pragma unroll
            for (int k = 0; k < 4; k++) {
                u32 ka = (u32)(k * 32);
                u32 ah[8], bh[8];
                ldsm4(aHiB + swz(arow + ka),        ah[0], ah[1], ah[2], ah[3]);
                ldsm4(aHiB + swz(arow + 2048 + ka), ah[4], ah[5], ah[6], ah[7]);
                ldsm4(bHiB + swz(brow + ka),        bh[0], bh[1], bh[2], bh[3]);
                ldsm4(bHiB + swz(brow + 2048 + ka), bh[4], bh[5], bh[6], bh[7]);
                #pragma unroll
                for (int mt = 0; mt < 2; mt++) {
                    #pragma unroll
                    for (int nt = 0; nt < 4; nt++) {
                        mma_f16(acc[mt][nt][0], acc[mt][nt][1], acc[mt][nt][2], acc[mt][nt][3],
                                ah[mt*4], ah[mt*4+1], ah[mt*4+2], ah[mt*4+3], bh[nt*2], bh[nt*2+1]);
                    }
                }
            }
        }
    }

    // ================= epilogue =================
    {
        int mbase = (wid & 3) * 32, nbase = (wid >> 2) * 32;
        #pragma unroll
        for (int mt = 0; mt < 2; mt++) {
            #pragma unroll
            for (int nt = 0; nt < 4; nt++) {
                int pix = p0 + mbase + mt * 16 + (ln >> 2);
                int oc  = nbase + nt * 8 + (ln & 3) * 2;
                float b0 = __ldg(bker + oc), b1 = __ldg(bker + oc + 1);
                size_t base = ((size_t)(b * 64 + oc)) * NPIX + pix;
                out[base]            = acc[mt][nt][0] + b0;
                out[base + NPIX]     = acc[mt][nt][1] + b1;
                out[base + 8]        = acc[mt][nt][2] + b0;
                out[base + NPIX + 8] = acc[mt][nt][3] + b1;
            }
        }
    }
}

// ================= launch =================
extern "C" void kernel_launch(void* const* d_in, const int* in_sizes, int n_in,
                              void* d_out, int out_size) {
    const float* x     = (const float*)d_in[0];
    const float* w_off = (const float*)d_in[1];
    const float* b_off = (const float*)d_in[2];
    const float* w_ker = (const float*)d_in[3];
    const float* b_ker = (const float*)d_in[4];
    float* out = (float*)d_out;

    cudaFuncSetAttribute(k_main, cudaFuncAttributeMaxDynamicSharedMemorySize, SMEM_MAIN);

    k_transpose<<<dim3(NPIX / 64, BB), 256>>>(x);
    k_prep<<<(9 * 4096 + 9 * 2048 + 255) / 256, 256>>>(w_ker, w_off);
    k_main<<<dim3(NPIX / 128, BB), 256, SMEM_MAIN>>>(b_off, b_ker, out);
}

// round 15
// speedup vs baseline: 1.5726x; 1.0704x over previous
#include <cuda_runtime.h>
#include <cuda_bf16.h>
#include <cuda_fp16.h>

// ---------------- constants ----------------
#define HH 96
#define WW 96
#define NPIX 9216
#define BB 8

typedef unsigned int u32;
typedef unsigned long long ull;

// ---------------- scratch ----------------
__device__ float g_xt[BB * NPIX * 64];            // x channels-last f32
__device__ unsigned short g_wf[9 * 64 * 64];      // main-conv B fp16 (RN), swizzled [n][oc][ch]
__device__ unsigned short g_wof[9 * 32 * 64];     // offset-conv B fp16 (24 rows used, padded 32)

// ---------------- helpers ----------------
__device__ __forceinline__ u32 s2u(const void* p) {
    u32 a; asm("{ .reg .u64 t; cvta.to.shared.u64 t, %1; cvt.u32.u64 %0, t; }" : "=r"(a) : "l"(p));
    return a;
}
__device__ __forceinline__ u32 swz(u32 b) { return b ^ ((b >> 3) & 0x70); }

__device__ __forceinline__ void ldsm4(u32 a, u32& r0, u32& r1, u32& r2, u32& r3) {
    asm volatile("ldmatrix.sync.aligned.m8n8.x4.shared.b16 {%0,%1,%2,%3}, [%4];"
                 : "=r"(r0), "=r"(r1), "=r"(r2), "=r"(r3) : "r"(a));
}
__device__ __forceinline__ void mma_f16(float& d0, float& d1, float& d2, float& d3,
                                        u32 a0, u32 a1, u32 a2, u32 a3, u32 b0, u32 b1) {
    asm volatile("mma.sync.aligned.m16n8k16.row.col.f32.f16.f16.f32 "
                 "{%0,%1,%2,%3},{%4,%5,%6,%7},{%8,%9},{%0,%1,%2,%3};"
                 : "+f"(d0), "+f"(d1), "+f"(d2), "+f"(d3)
                 : "r"(a0), "r"(a1), "r"(a2), "r"(a3), "r"(b0), "r"(b1));
}
__device__ __forceinline__ void sts128(u32 a, u32 x, u32 y, u32 z, u32 w) {
    asm volatile("st.shared.v4.b32 [%0],{%1,%2,%3,%4};" :: "r"(a), "r"(x), "r"(y), "r"(z), "r"(w) : "memory");
}
__device__ __forceinline__ void sts64(u32 a, u32 x, u32 y) {
    asm volatile("st.shared.v2.b32 [%0],{%1,%2};" :: "r"(a), "r"(x), "r"(y) : "memory");
}
__device__ __forceinline__ u32 f16x2(float lo, float hi) {   // lo -> low half
    u32 r; asm("cvt.rn.f16x2.f32 %0, %1, %2;" : "=r"(r) : "f"(hi), "f"(lo));
    return r;
}
__device__ __forceinline__ ull pack2(float lo, float hi) {
    ull r; asm("mov.b64 %0, {%1,%2};" : "=l"(r) : "f"(lo), "f"(hi)); return r;
}
__device__ __forceinline__ void unpack2(ull v, float& lo, float& hi) {
    asm("mov.b64 {%0,%1}, %2;" : "=f"(lo), "=f"(hi) : "l"(v));
}
__device__ __forceinline__ ull mul2(ull a, ull b) {
    ull r; asm("mul.rn.f32x2 %0, %1, %2;" : "=l"(r) : "l"(a), "l"(b)); return r;
}
__device__ __forceinline__ void fma2(ull& d, ull a, ull b) {
    asm("fma.rn.f32x2 %0, %1, %2, %0;" : "+l"(d) : "l"(a), "l"(b));
}

// ================= K1: transpose x (b,c,h,w) -> (b,hw,c) =================
__global__ __launch_bounds__(256) void k_transpose(const float* __restrict__ x) {
    __shared__ float tile[64][65];
    int b  = blockIdx.y;
    int p0 = blockIdx.x << 6;
    int t  = threadIdx.x;
    #pragma unroll
    for (int i = t; i < 4096; i += 256) {
        int c = i >> 6, p = i & 63;
        tile[c][p] = x[((size_t)(b * 64 + c)) * NPIX + p0 + p];
    }
    __syncthreads();
    #pragma unroll
    for (int i = t; i < 4096; i += 256) {
        int p = i >> 6, c = i & 63;
        g_xt[((size_t)b * NPIX + p0 + p) * 64 + c] = tile[c][p];
    }
}

// ================= K0: weight prep (fp16 RN, pre-swizzled) =================
__global__ __launch_bounds__(256) void k_prep(const float* __restrict__ wker,
                                              const float* __restrict__ wof) {
    int i = blockIdx.x * 256 + threadIdx.x;
    if (i < 9 * 4096) {
        int n = i >> 12, r = i & 4095, oc = r >> 6, ch = r & 63;
        float v = wker[(oc * 64 + ch) * 9 + n];
        __half h = __float2half_rn(v);
        u32 sw = swz((u32)(oc * 128 + ch * 2)) >> 1;
        g_wf[n * 4096 + sw] = *(unsigned short*)&h;
    } else {
        int j = i - 9 * 4096;
        if (j < 9 * 2048) {
            int n = j >> 11, r = j & 2047, oc = r >> 6, ch = r & 63;
            float v = (oc < 18) ? wof[(oc * 64 + ch) * 9 + n] : 0.f;
            __half h = __float2half_rn(v);
            u32 sw = swz((u32)(oc * 128 + ch * 2)) >> 1;
            g_wof[n * 2048 + sw] = *(unsigned short*)&h;
        }
    }
}

// ================= K_MAIN =================
// smem: A fp16 tile 16K, B fp16 tile 8K, meta MO 18K + MW 18K = 60K -> 2 CTAs/SM
#define A_F     0
#define B_F     16384
#define OFF_MO  24576
#define OFF_MW  43008
#define SMEM_MAIN 61440

__global__ __launch_bounds__(256, 2) void k_main(const float* __restrict__ bof,
                                                 const float* __restrict__ bker,
                                                 float* __restrict__ out) {
    extern __shared__ char smc[];
    u32 sb = s2u(smc);
    int t = threadIdx.x, wid = t >> 5, ln = t & 31;
    int b = blockIdx.y;
    int p0 = blockIdx.x * 128;
    const float* xb = g_xt + (size_t)b * NPIX * 64;
    u32 aF = sb + A_F, bF = sb + B_F;

    // ========== PHASE 0: offset conv (fp16 single-term), all 8 warps ==========
    float acc0[3][4];
    #pragma unroll
    for (int nt = 0; nt < 3; nt++)
        #pragma unroll
        for (int j = 0; j < 4; j++) acc0[nt][j] = 0.f;

    {
        int lp = t >> 1, q = t & 1;
        int pix = p0 + lp, hh = pix / 96, ww = pix - hh * 96;

        for (int tap = 0; tap < 9; tap++) {
            __syncthreads();
            // stage B fp16 for this tap: 4KB (32 rows x 64 ch)
            ((uint4*)(smc + B_F))[t] = ((const uint4*)g_wof + tap * 256)[t];
            // A-build: f32 -> fp16 RN, single tile
            {
                int sh_ = hh + tap / 3 - 1, sw_ = ww + tap % 3 - 1;
                bool ok = ((unsigned)sh_ < 96u) & ((unsigned)sw_ < 96u);
                float4 v[8];
                if (ok) {
                    const float4* src = (const float4*)(xb + (size_t)(sh_ * 96 + sw_) * 64) + q * 8;
                    #pragma unroll
                    for (int j = 0; j < 8; j++) v[j] = src[j];
                } else {
                    #pragma unroll
                    for (int j = 0; j < 8; j++) v[j] = make_float4(0.f, 0.f, 0.f, 0.f);
                }
                u32 rowb = (u32)(lp * 128 + q * 64);
                #pragma unroll
                for (int j = 0; j < 4; j++) {
                    u32 sa = swz(rowb + j * 16);
                    sts128(aF + sa, f16x2(v[2*j].x, v[2*j].y), f16x2(v[2*j].z, v[2*j].w),
                                    f16x2(v[2*j+1].x, v[2*j+1].y), f16x2(v[2*j+1].z, v[2*j+1].w));
                }
            }
            __syncthreads();
            {
                u32 arow = (u32)((wid * 16 + (ln & 15)) * 128 + ((ln >> 4) * 16));
                u32 brow = (u32)(((((ln >> 4) << 3) + (ln & 7))) * 128 + (((ln >> 3) & 1) * 16));
                #pragma unroll
                for (int k = 0; k < 4; k++) {
                    u32 ka = (u32)(k * 32);
                    u32 ah[4], bh[8];
                    ldsm4(aF + swz(arow + ka), ah[0], ah[1], ah[2], ah[3]);
                    ldsm4(bF + swz(brow + ka), bh[0], bh[1], bh[2], bh[3]);
                    ldsm4(bF + swz(brow + 2048 + ka), bh[4], bh[5], bh[6], bh[7]);
                    #pragma unroll
                    for (int nt = 0; nt < 3; nt++)
                        mma_f16(acc0[nt][0], acc0[nt][1], acc0[nt][2], acc0[nt][3],
                                ah[0], ah[1], ah[2], ah[3], bh[nt*2], bh[nt*2+1]);
                }
            }
        }
    }
    __syncthreads();
    {
        float* dst = (float*)(smc + A_F);
        int pr = wid * 16 + (ln >> 2);
        int pc = (ln & 3) * 2;
        #pragma unroll
        for (int nt = 0; nt < 3; nt++) {
            dst[pr * 24 + nt * 8 + pc]           = acc0[nt][0];
            dst[pr * 24 + nt * 8 + pc + 1]       = acc0[nt][1];
            dst[(pr + 8) * 24 + nt * 8 + pc]     = acc0[nt][2];
            dst[(pr + 8) * 24 + nt * 8 + pc + 1] = acc0[nt][3];
        }
    }
    __syncthreads();
    {
        const float* dsm = (const float*)(smc + A_F);
        int4*   mo = (int4*)(smc + OFF_MO);
        float4* mw = (float4*)(smc + OFF_MW);
        for (int i = t; i < 1152; i += 256) {
            int lp = i / 9, n = i - lp * 9;
            int pix = p0 + lp, hh = pix / 96, ww = pix - hh * 96;
            float ox = dsm[lp * 24 + n]     + __ldg(bof + n);
            float oy = dsm[lp * 24 + 9 + n] + __ldg(bof + 9 + n);
            float px = (float)(hh + n / 3 - 1) + ox;
            float py = (float)(ww + n % 3 - 1) + oy;
            px = fminf(fmaxf(px, -10000.f), 10000.f);
            py = fminf(fmaxf(py, -10000.f), 10000.f);
            float fx = floorf(px), fy = floorf(py);
            float lx = px - fx, ly = py - fy;
            int x0 = (int)fx, y0 = (int)fy, x1 = x0 + 1, y1 = y0 + 1;
            float w00 = (1.f - lx) * (1.f - ly);
            float w10 = lx * (1.f - ly);
            float w01 = (1.f - lx) * ly;
            float w11 = lx * ly;
            if ((unsigned)x0 >= 96u) { w00 = 0.f; w01 = 0.f; }
            if ((unsigned)x1 >= 96u) { w10 = 0.f; w11 = 0.f; }
            if ((unsigned)y0 >= 96u) { w00 = 0.f; w10 = 0.f; }
            if ((unsigned)y1 >= 96u) { w01 = 0.f; w11 = 0.f; }
            int cx0 = min(max(x0, 0), 95), cx1 = min(max(x1, 0), 95);
            int cy0 = min(max(y0, 0), 95), cy1 = min(max(y1, 0), 95);
            mo[i] = make_int4((cx0 * 96 + cy0) * 64, (cx1 * 96 + cy0) * 64,
                              (cx0 * 96 + cy1) * 64, (cx1 * 96 + cy1) * 64);
            mw[i] = make_float4(w00, w10, w01, w11);
        }
    }

    // ================= PHASE 1: sampled main conv (single-term fp16) =================
    float acc[2][4][4];
    #pragma unroll
    for (int mt = 0; mt < 2; mt++)
        #pragma unroll
        for (int nt = 0; nt < 4; nt++)
            #pragma unroll
            for (int j = 0; j < 4; j++) acc[mt][nt][j] = 0.f;

    int l8 = ln & 7, g4 = ln >> 3;     // lane -> (pixel-in-group g4, 4-ch slice l8)
    const int4*   mo = (const int4*)(smc + OFF_MO);
    const float4* mw = (const float4*)(smc + OFF_MW);

    for (int n = 0; n < 9; n++) {
        __syncthreads();
        {
            // stage fp16 weights for this n: 8KB
            const uint4* sw4 = (const uint4*)g_wf + n * 512;
            uint4* dh = (uint4*)(smc + B_F);
            dh[t] = sw4[t]; dh[t + 256] = sw4[t + 256];
        }
        // sample: warp = 4 pixels x 8 lanes; lane l8 owns channels [l8*4,+4) and [32+l8*4,+4)
        #pragma unroll
        for (int i = 0; i < 4; i++) {
            int lp = wid * 16 + i * 4 + g4;
            int mi = lp * 9 + n;
            int4   o4 = mo[mi];
            float4 w4 = mw[mi];
            const float* pA = xb + o4.x + l8 * 4;
            const float* pB = xb + o4.y + l8 * 4;
            const float* pC = xb + o4.z + l8 * 4;
            const float* pD = xb + o4.w + l8 * 4;
            float4 A0 = *(const float4*)pA, A1 = *(const float4*)(pA + 32);
            float4 B0 = *(const float4*)pB, B1 = *(const float4*)(pB + 32);
            float4 C0 = *(const float4*)pC, C1 = *(const float4*)(pC + 32);
            float4 D0 = *(const float4*)pD, D1 = *(const float4*)(pD + 32);
            ull W00 = pack2(w4.x, w4.x), W10 = pack2(w4.y, w4.y);
            ull W01 = pack2(w4.z, w4.z), W11 = pack2(w4.w, w4.w);
            ull r0 = mul2(pack2(A0.x, A0.y), W00);
            ull r1 = mul2(pack2(A0.z, A0.w), W00);
            ull r2 = mul2(pack2(A1.x, A1.y), W00);
            ull r3 = mul2(pack2(A1.z, A1.w), W00);
            fma2(r0, pack2(B0.x, B0.y), W10); fma2(r1, pack2(B0.z, B0.w), W10);
            fma2(r2, pack2(B1.x, B1.y), W10); fma2(r3, pack2(B1.z, B1.w), W10);
            fma2(r0, pack2(C0.x, C0.y), W01); fma2(r1, pack2(C0.z, C0.w), W01);
            fma2(r2, pack2(C1.x, C1.y), W01); fma2(r3, pack2(C1.z, C1.w), W01);
            fma2(r0, pack2(D0.x, D0.y), W11); fma2(r1, pack2(D0.z, D0.w), W11);
            fma2(r2, pack2(D1.x, D1.y), W11); fma2(r3, pack2(D1.z, D1.w), W11);
            float s0, s1, s2, s3, s4, s5, s6, s7;
            unpack2(r0, s0, s1); unpack2(r1, s2, s3);
            unpack2(r2, s4, s5); unpack2(r3, s6, s7);
            u32 sa0 = swz((u32)(lp * 128 + l8 * 8));
            u32 sa1 = swz((u32)(lp * 128 + 64 + l8 * 8));
            sts64(aF + sa0, f16x2(s0, s1), f16x2(s2, s3));
            sts64(aF + sa1, f16x2(s4, s5), f16x2(s6, s7));
        }
        __syncthreads();
        {
            int mbase = (wid & 3) * 32, nbase = (wid >> 2) * 32;
            u32 arow = (u32)((mbase + (ln & 15)) * 128 + ((ln >> 4) * 16));
            u32 brow = (u32)((nbase + ((ln >> 4) << 3) + (ln & 7)) * 128 + (((ln >> 3) & 1) * 16));
            #pragma unroll
            for (int k = 0; k < 4; k++) {
                u32 ka = (u32)(k * 32);
                u32 ah[8], bh[8];
                ldsm4(aF + swz(arow + ka),        ah[0], ah[1], ah[2], ah[3]);
                ldsm4(aF + swz(arow + 2048 + ka), ah[4], ah[5], ah[6], ah[7]);
                ldsm4(bF + swz(brow + ka),        bh[0], bh[1], bh[2], bh[3]);
                ldsm4(bF + swz(brow + 2048 + ka), bh[4], bh[5], bh[6], bh[7]);
                #pragma unroll
                for (int mt = 0; mt < 2; mt++) {
                    #pragma unroll
                    for (int nt = 0; nt < 4; nt++) {
                        mma_f16(acc[mt][nt][0], acc[mt][nt][1], acc[mt][nt][2], acc[mt][nt][3],
                                ah[mt*4], ah[mt*4+1], ah[mt*4+2], ah[mt*4+3], bh[nt*2], bh[nt*2+1]);
                    }
                }
            }
        }
    }

    // ================= epilogue =================
    {
        int mbase = (wid & 3) * 32, nbase = (wid >> 2) * 32;
        #pragma unroll
        for (int mt = 0; mt < 2; mt++) {
            #pragma unroll
            for (int nt = 0; nt < 4; nt++) {
                int pix = p0 + mbase + mt * 16 + (ln >> 2);
                int oc  = nbase + nt * 8 + (ln & 3) * 2;
                float b0 = __ldg(bker + oc), b1 = __ldg(bker + oc + 1);
                size_t base = ((size_t)(b * 64 + oc)) * NPIX + pix;
                out[base]            = acc[mt][nt][0] + b0;
                out[base + NPIX]     = acc[mt][nt][1] + b1;
                out[base + 8]        = acc[mt][nt][2] + b0;
                out[base + NPIX + 8] = acc[mt][nt][3] + b1;
            }
        }
    }
}

// ================= launch =================
extern "C" void kernel_launch(void* const* d_in, const int* in_sizes, int n_in,
                              void* d_out, int out_size) {
    const float* x     = (const float*)d_in[0];
    const float* w_off = (const float*)d_in[1];
    const float* b_off = (const float*)d_in[2];
    const float* w_ker = (const float*)d_in[3];
    const float* b_ker = (const float*)d_in[4];
    float* out = (float*)d_out;

    cudaFuncSetAttribute(k_main, cudaFuncAttributeMaxDynamicSharedMemorySize, SMEM_MAIN);

    k_transpose<<<dim3(NPIX / 64, BB), 256>>>(x);
    k_prep<<<(9 * 4096 + 9 * 2048 + 255) / 256, 256>>>(w_ker, w_off);
    k_main<<<dim3(NPIX / 128, BB), 256, SMEM_MAIN>>>(b_off, b_ker, out);
}

// round 16
// speedup vs baseline: 2.0756x; 1.3199x over previous
#include <cuda_runtime.h>
#include <cuda_bf16.h>
#include <cuda_fp16.h>

// ---------------- constants ----------------
#define HH 96
#define WW 96
#define NPIX 9216
#define BB 8

typedef unsigned int u32;
typedef unsigned long long ull;

// ---------------- scratch ----------------
__device__ float g_xt[BB * NPIX * 64];            // x channels-last f32
__device__ u32   g_xh[BB * NPIX * 32];            // x channels-last fp16 (packed pairs)
__device__ unsigned short g_wf[9 * 64 * 64];      // main-conv B fp16 (RN), swizzled [n][oc][ch]
__device__ unsigned short g_wof[9 * 32 * 64];     // offset-conv B fp16 (24 rows used, padded 32)

// ---------------- helpers ----------------
__device__ __forceinline__ u32 s2u(const void* p) {
    u32 a; asm("{ .reg .u64 t; cvta.to.shared.u64 t, %1; cvt.u32.u64 %0, t; }" : "=r"(a) : "l"(p));
    return a;
}
__device__ __forceinline__ u32 swz(u32 b) { return b ^ ((b >> 3) & 0x70); }

__device__ __forceinline__ void ldsm4(u32 a, u32& r0, u32& r1, u32& r2, u32& r3) {
    asm volatile("ldmatrix.sync.aligned.m8n8.x4.shared.b16 {%0,%1,%2,%3}, [%4];"
                 : "=r"(r0), "=r"(r1), "=r"(r2), "=r"(r3) : "r"(a));
}
__device__ __forceinline__ void mma_f16(float& d0, float& d1, float& d2, float& d3,
                                        u32 a0, u32 a1, u32 a2, u32 a3, u32 b0, u32 b1) {
    asm volatile("mma.sync.aligned.m16n8k16.row.col.f32.f16.f16.f32 "
                 "{%0,%1,%2,%3},{%4,%5,%6,%7},{%8,%9},{%0,%1,%2,%3};"
                 : "+f"(d0), "+f"(d1), "+f"(d2), "+f"(d3)
                 : "r"(a0), "r"(a1), "r"(a2), "r"(a3), "r"(b0), "r"(b1));
}
__device__ __forceinline__ void sts128(u32 a, u32 x, u32 y, u32 z, u32 w) {
    asm volatile("st.shared.v4.b32 [%0],{%1,%2,%3,%4};" :: "r"(a), "r"(x), "r"(y), "r"(z), "r"(w) : "memory");
}
__device__ __forceinline__ void sts64(u32 a, u32 x, u32 y) {
    asm volatile("st.shared.v2.b32 [%0],{%1,%2};" :: "r"(a), "r"(x), "r"(y) : "memory");
}
__device__ __forceinline__ u32 f16x2(float lo, float hi) {   // lo -> low half
    u32 r; asm("cvt.rn.f16x2.f32 %0, %1, %2;" : "=r"(r) : "f"(hi), "f"(lo));
    return r;
}
__device__ __forceinline__ ull pack2(float lo, float hi) {
    ull r; asm("mov.b64 %0, {%1,%2};" : "=l"(r) : "f"(lo), "f"(hi)); return r;
}
__device__ __forceinline__ void unpack2(ull v, float& lo, float& hi) {
    asm("mov.b64 {%0,%1}, %2;" : "=f"(lo), "=f"(hi) : "l"(v));
}
__device__ __forceinline__ ull mul2(ull a, ull b) {
    ull r; asm("mul.rn.f32x2 %0, %1, %2;" : "=l"(r) : "l"(a), "l"(b)); return r;
}
__device__ __forceinline__ void fma2(ull& d, ull a, ull b) {
    asm("fma.rn.f32x2 %0, %1, %2, %0;" : "+l"(d) : "l"(a), "l"(b));
}

// ================= K1: transpose x + fp16 image emit =================
__global__ __launch_bounds__(256) void k_transpose(const float* __restrict__ x) {
    __shared__ float tile[64][65];
    int b  = blockIdx.y;
    int p0 = blockIdx.x << 6;
    int t  = threadIdx.x;
    #pragma unroll
    for (int i = t; i < 4096; i += 256) {
        int c = i >> 6, p = i & 63;
        tile[c][p] = x[((size_t)(b * 64 + c)) * NPIX + p0 + p];
    }
    __syncthreads();
    #pragma unroll
    for (int i = t; i < 4096; i += 256) {
        int p = i >> 6, c = i & 63;
        g_xt[((size_t)b * NPIX + p0 + p) * 64 + c] = tile[c][p];
    }
    #pragma unroll
    for (int i = t; i < 2048; i += 256) {
        int p = i >> 5, cp = i & 31;
        g_xh[((size_t)b * NPIX + p0 + p) * 32 + cp] =
            f16x2(tile[cp * 2][p], tile[cp * 2 + 1][p]);
    }
}

// ================= K0: weight prep (fp16 RN, pre-swizzled) =================
__global__ __launch_bounds__(256) void k_prep(const float* __restrict__ wker,
                                              const float* __restrict__ wof) {
    int i = blockIdx.x * 256 + threadIdx.x;
    if (i < 9 * 4096) {
        int n = i >> 12, r = i & 4095, oc = r >> 6, ch = r & 63;
        float v = wker[(oc * 64 + ch) * 9 + n];
        __half h = __float2half_rn(v);
        u32 sw = swz((u32)(oc * 128 + ch * 2)) >> 1;
        g_wf[n * 4096 + sw] = *(unsigned short*)&h;
    } else {
        int j = i - 9 * 4096;
        if (j < 9 * 2048) {
            int n = j >> 11, r = j & 2047, oc = r >> 6, ch = r & 63;
            float v = (oc < 18) ? wof[(oc * 64 + ch) * 9 + n] : 0.f;
            __half h = __float2half_rn(v);
            u32 sw = swz((u32)(oc * 128 + ch * 2)) >> 1;
            g_wof[n * 2048 + sw] = *(unsigned short*)&h;
        }
    }
}

// ================= K_MAIN =================
// smem: A ring 2 x 16K, B ring 2 x 8K, compact meta (4.5K + 9K) = 62976 B
#define AF(s)   ((s) * 16384)
#define BF(s)   (32768 + (s) * 8192)
#define OFF_MXY  49152
#define OFF_MLXY 53760
#define SMEM_MAIN 62976

// phase-0 A build: pure fp16 copy from g_xh (4 LDG.128 + 4 STS.128)
__device__ __forceinline__ void build_a0(const u32* __restrict__ xh,
                                         int hh, int ww, int tap,
                                         int lp, int q, u32 aF) {
    int sh_ = hh + tap / 3 - 1, sw_ = ww + tap % 3 - 1;
    bool ok = ((unsigned)sh_ < 96u) & ((unsigned)sw_ < 96u);
    uint4 v[4];
    if (ok) {
        const uint4* src = (const uint4*)(xh + (size_t)(sh_ * 96 + sw_) * 32) + q * 4;
        #pragma unroll
        for (int j = 0; j < 4; j++) v[j] = src[j];
    } else {
        #pragma unroll
        for (int j = 0; j < 4; j++) v[j] = make_uint4(0, 0, 0, 0);
    }
    u32 rowb = (u32)(lp * 128 + q * 64);
    #pragma unroll
    for (int j = 0; j < 4; j++) {
        u32 sa = swz(rowb + j * 16);
        sts128(aF + sa, v[j].x, v[j].y, v[j].z, v[j].w);
    }
}

// phase-1 sampler: compact meta, fp32 blend, fp16 output
__device__ __forceinline__ void sample_pix(const float* __restrict__ xb,
                                           const int* __restrict__ mxy,
                                           const float2* __restrict__ mlxy,
                                           int lp, int n, int l8, u32 aF) {
    int mi = lp * 9 + n;
    int xy = mxy[mi];
    float2 l = mlxy[mi];
    int x0 = xy >> 16, y0 = (xy << 16) >> 16;
    int x1 = x0 + 1, y1 = y0 + 1;
    float lx = l.x, ly = l.y;
    float w00 = (1.f - lx) * (1.f - ly);
    float w10 = lx * (1.f - ly);
    float w01 = (1.f - lx) * ly;
    float w11 = lx * ly;
    if ((unsigned)x0 >= 96u) { w00 = 0.f; w01 = 0.f; }
    if ((unsigned)x1 >= 96u) { w10 = 0.f; w11 = 0.f; }
    if ((unsigned)y0 >= 96u) { w00 = 0.f; w10 = 0.f; }
    if ((unsigned)y1 >= 96u) { w01 = 0.f; w11 = 0.f; }
    int cx0 = min(max(x0, 0), 95), cx1 = min(max(x1, 0), 95);
    int cy0 = min(max(y0, 0), 95), cy1 = min(max(y1, 0), 95);
    const float* pA = xb + (cx0 * 96 + cy0) * 64 + l8 * 4;
    const float* pB = xb + (cx1 * 96 + cy0) * 64 + l8 * 4;
    const float* pC = xb + (cx0 * 96 + cy1) * 64 + l8 * 4;
    const float* pD = xb + (cx1 * 96 + cy1) * 64 + l8 * 4;
    float4 A0 = *(const float4*)pA, A1 = *(const float4*)(pA + 32);
    float4 B0 = *(const float4*)pB, B1 = *(const float4*)(pB + 32);
    float4 C0 = *(const float4*)pC, C1 = *(const float4*)(pC + 32);
    float4 D0 = *(const float4*)pD, D1 = *(const float4*)(pD + 32);
    ull W00 = pack2(w00, w00), W10 = pack2(w10, w10);
    ull W01 = pack2(w01, w01), W11 = pack2(w11, w11);
    ull r0 = mul2(pack2(A0.x, A0.y), W00);
    ull r1 = mul2(pack2(A0.z, A0.w), W00);
    ull r2 = mul2(pack2(A1.x, A1.y), W00);
    ull r3 = mul2(pack2(A1.z, A1.w), W00);
    fma2(r0, pack2(B0.x, B0.y), W10); fma2(r1, pack2(B0.z, B0.w), W10);
    fma2(r2, pack2(B1.x, B1.y), W10); fma2(r3, pack2(B1.z, B1.w), W10);
    fma2(r0, pack2(C0.x, C0.y), W01); fma2(r1, pack2(C0.z, C0.w), W01);
    fma2(r2, pack2(C1.x, C1.y), W01); fma2(r3, pack2(C1.z, C1.w), W01);
    fma2(r0, pack2(D0.x, D0.y), W11); fma2(r1, pack2(D0.z, D0.w), W11);
    fma2(r2, pack2(D1.x, D1.y), W11); fma2(r3, pack2(D1.z, D1.w), W11);
    float s0, s1, s2, s3, s4, s5, s6, s7;
    unpack2(r0, s0, s1); unpack2(r1, s2, s3);
    unpack2(r2, s4, s5); unpack2(r3, s6, s7);
    u32 sa0 = swz((u32)(lp * 128 + l8 * 8));
    u32 sa1 = swz((u32)(lp * 128 + 64 + l8 * 8));
    sts64(aF + sa0, f16x2(s0, s1), f16x2(s2, s3));
    sts64(aF + sa1, f16x2(s4, s5), f16x2(s6, s7));
}

__global__ __launch_bounds__(256, 2) void k_main(const float* __restrict__ bof,
                                                 const float* __restrict__ bker,
                                                 float* __restrict__ out) {
    extern __shared__ char smc[];
    u32 sb = s2u(smc);
    int t = threadIdx.x, wid = t >> 5, ln = t & 31;
    int b = blockIdx.y;
    int p0 = blockIdx.x * 128;
    const float* xb = g_xt + (size_t)b * NPIX * 64;
    const u32*   xh = g_xh + (size_t)b * NPIX * 32;

    // ========== PHASE 0: offset conv (fp16 single-term), double-buffered ==========
    float acc0[3][4];
    #pragma unroll
    for (int nt = 0; nt < 3; nt++)
        #pragma unroll
        for (int j = 0; j < 4; j++) acc0[nt][j] = 0.f;

    {
        int lp = t >> 1, q = t & 1;
        int pix = p0 + lp, hh = pix / 96, ww = pix - hh * 96;
        u32 arow = (u32)((wid * 16 + (ln & 15)) * 128 + ((ln >> 4) * 16));
        u32 brow = (u32)(((((ln >> 4) << 3) + (ln & 7))) * 128 + (((ln >> 3) & 1) * 16));

        // prologue: build A(0), stage B(0)
        ((uint4*)(smc + BF(0)))[t] = ((const uint4*)g_wof)[t];
        build_a0(xh, hh, ww, 0, lp, q, sb + AF(0));
        __syncthreads();

        for (int tap = 0; tap < 9; tap++) {
            int s = tap & 1;
            if (tap < 8) {
                ((uint4*)(smc + BF(1 - s)))[t] = ((const uint4*)g_wof)[(tap + 1) * 256 + t];
                build_a0(xh, hh, ww, tap + 1, lp, q, sb + AF(1 - s));
            }
            {
                u32 aF = sb + AF(s), bF = sb + BF(s);
                #pragma unroll
                for (int k = 0; k < 4; k++) {
                    u32 ka = (u32)(k * 32);
                    u32 ah[4], bh[8];
                    ldsm4(aF + swz(arow + ka), ah[0], ah[1], ah[2], ah[3]);
                    ldsm4(bF + swz(brow + ka), bh[0], bh[1], bh[2], bh[3]);
                    ldsm4(bF + swz(brow + 2048 + ka), bh[4], bh[5], bh[6], bh[7]);
                    #pragma unroll
                    for (int nt = 0; nt < 3; nt++)
                        mma_f16(acc0[nt][0], acc0[nt][1], acc0[nt][2], acc0[nt][3],
                                ah[0], ah[1], ah[2], ah[3], bh[nt*2], bh[nt*2+1]);
                }
            }
            __syncthreads();
        }
    }
    // stage offset outputs as f32 (reuse A region)
    {
        float* dst = (float*)(smc + AF(0));
        int pr = wid * 16 + (ln >> 2);
        int pc = (ln & 3) * 2;
        #pragma unroll
        for (int nt = 0; nt < 3; nt++) {
            dst[pr * 24 + nt * 8 + pc]           = acc0[nt][0];
            dst[pr * 24 + nt * 8 + pc + 1]       = acc0[nt][1];
            dst[(pr + 8) * 24 + nt * 8 + pc]     = acc0[nt][2];
            dst[(pr + 8) * 24 + nt * 8 + pc + 1] = acc0[nt][3];
        }
    }
    __syncthreads();
    // bilinear meta (compact: packed int corner + float2 fractions)
    {
        const float* dsm = (const float*)(smc + AF(0));
        int*    mxy  = (int*)(smc + OFF_MXY);
        float2* mlxy = (float2*)(smc + OFF_MLXY);
        for (int i = t; i < 1152; i += 256) {
            int lp = i / 9, n = i - lp * 9;
            int pix = p0 + lp, hh = pix / 96, ww = pix - hh * 96;
            float ox = dsm[lp * 24 + n]     + __ldg(bof + n);
            float oy = dsm[lp * 24 + 9 + n] + __ldg(bof + 9 + n);
            float px = (float)(hh + n / 3 - 1) + ox;
            float py = (float)(ww + n % 3 - 1) + oy;
            px = fminf(fmaxf(px, -10000.f), 10000.f);
            py = fminf(fmaxf(py, -10000.f), 10000.f);
            float fx = floorf(px), fy = floorf(py);
            int x0 = (int)fx, y0 = (int)fy;
            mxy[i]  = (x0 << 16) | (y0 & 0xffff);
            mlxy[i] = make_float2(px - fx, py - fy);
        }
    }
    __syncthreads();

    // ========== PHASE 1: sampled main conv, double-buffered ==========
    const int*    mxy  = (const int*)(smc + OFF_MXY);
    const float2* mlxy = (const float2*)(smc + OFF_MLXY);
    int l8 = ln & 7, g4 = ln >> 3;

    float acc[2][4][4];
    #pragma unroll
    for (int mt = 0; mt < 2; mt++)
        #pragma unroll
        for (int nt = 0; nt < 4; nt++)
            #pragma unroll
            for (int j = 0; j < 4; j++) acc[mt][nt][j] = 0.f;

    int mbase = (wid & 3) * 32, nbase = (wid >> 2) * 32;
    u32 arow = (u32)((mbase + (ln & 15)) * 128 + ((ln >> 4) * 16));
    u32 brow = (u32)((nbase + ((ln >> 4) << 3) + (ln & 7)) * 128 + (((ln >> 3) & 1) * 16));

    // prologue: stage B(0) + sample(0) into stage 0
    {
        const uint4* sw4 = (const uint4*)g_wf;
        ((uint4*)(smc + BF(0)))[t]       = sw4[t];
        ((uint4*)(smc + BF(0)))[t + 256] = sw4[t + 256];
        #pragma unroll
        for (int i = 0; i < 4; i++) {
            int lp = wid * 16 + i * 4 + g4;
            sample_pix(xb, mxy, mlxy, lp, 0, l8, sb + AF(0));
        }
    }
    __syncthreads();

    for (int n = 0; n < 9; n++) {
        int s = n & 1;
        if (n < 8) {
            const uint4* sw4 = (const uint4*)g_wf + (n + 1) * 512;
            ((uint4*)(smc + BF(1 - s)))[t]       = sw4[t];
            ((uint4*)(smc + BF(1 - s)))[t + 256] = sw4[t + 256];
            #pragma unroll
            for (int i = 0; i < 4; i++) {
                int lp = wid * 16 + i * 4 + g4;
                sample_pix(xb, mxy, mlxy, lp, n + 1, l8, sb + AF(1 - s));
            }
        }
        {
            u32 aF = sb + AF(s), bF = sb + BF(s);
            #pragma unroll
            for (int k = 0; k < 4; k++) {
                u32 ka = (u32)(k * 32);
                u32 ah[8], bh[8];
                ldsm4(aF + swz(arow + ka),        ah[0], ah[1], ah[2], ah[3]);
                ldsm4(aF + swz(arow + 2048 + ka), ah[4], ah[5], ah[6], ah[7]);
                ldsm4(bF + swz(brow + ka),        bh[0], bh[1], bh[2], bh[3]);
                ldsm4(bF + swz(brow + 2048 + ka), bh[4], bh[5], bh[6], bh[7]);
                #pragma unroll
                for (int mt = 0; mt < 2; mt++) {
                    #pragma unroll
                    for (int nt = 0; nt < 4; nt++) {
                        mma_f16(acc[mt][nt][0], acc[mt][nt][1], acc[mt][nt][2], acc[mt][nt][3],
                                ah[mt*4], ah[mt*4+1], ah[mt*4+2], ah[mt*4+3], bh[nt*2], bh[nt*2+1]);
                    }
                }
            }
        }
        __syncthreads();
    }

    // ================= epilogue =================
    {
        #pragma unroll
        for (int mt = 0; mt < 2; mt++) {
            #pragma unroll
            for (int nt = 0; nt < 4; nt++) {
                int pix = p0 + mbase + mt * 16 + (ln >> 2);
                int oc  = nbase + nt * 8 + (ln & 3) * 2;
                float b0 = __ldg(bker + oc), b1 = __ldg(bker + oc + 1);
                size_t base = ((size_t)(b * 64 + oc)) * NPIX + pix;
                out[base]            = acc[mt][nt][0] + b0;
                out[base + NPIX]     = acc[mt][nt][1] + b1;
                out[base + 8]        = acc[mt][nt][2] + b0;
                out[base + NPIX + 8] = acc[mt][nt][3] + b1;
            }
        }
    }
}

// ================= launch =================
extern "C" void kernel_launch(void* const* d_in, const int* in_sizes, int n_in,
                              void* d_out, int out_size) {
    const float* x     = (const float*)d_in[0];
    const float* w_off = (const float*)d_in[1];
    const float* b_off = (const float*)d_in[2];
    const float* w_ker = (const float*)d_in[3];
    const float* b_ker = (const float*)d_in[4];
    float* out = (float*)d_out;

    cudaFuncSetAttribute(k_main, cudaFuncAttributeMaxDynamicSharedMemorySize, SMEM_MAIN);

    k_transpose<<<dim3(NPIX / 64, BB), 256>>>(x);
    k_prep<<<(9 * 4096 + 9 * 2048 + 255) / 256, 256>>>(w_ker, w_off);
    k_main<<<dim3(NPIX / 128, BB), 256, SMEM_MAIN>>>(b_off, b_ker, out);
}

// round 17
// speedup vs baseline: 2.6286x; 1.2664x over previous
#include <cuda_runtime.h>
#include <cuda_bf16.h>
#include <cuda_fp16.h>

// ---------------- constants ----------------
#define HH 96
#define WW 96
#define NPIX 9216
#define BB 8

typedef unsigned int u32;
typedef unsigned long long ull;

// ---------------- scratch ----------------
__device__ u32   g_xh[BB * NPIX * 32];            // x channels-last fp16 (packed pairs)
__device__ unsigned short g_wf[9 * 64 * 64];      // main-conv B fp16 (RN), swizzled [n][oc][ch]
__device__ unsigned short g_wof[9 * 32 * 64];     // offset-conv B fp16 (24 rows used, padded 32)

// ---------------- helpers ----------------
__device__ __forceinline__ u32 s2u(const void* p) {
    u32 a; asm("{ .reg .u64 t; cvta.to.shared.u64 t, %1; cvt.u32.u64 %0, t; }" : "=r"(a) : "l"(p));
    return a;
}
__device__ __forceinline__ u32 swz(u32 b) { return b ^ ((b >> 3) & 0x70); }

__device__ __forceinline__ void ldsm4(u32 a, u32& r0, u32& r1, u32& r2, u32& r3) {
    asm volatile("ldmatrix.sync.aligned.m8n8.x4.shared.b16 {%0,%1,%2,%3}, [%4];"
                 : "=r"(r0), "=r"(r1), "=r"(r2), "=r"(r3) : "r"(a));
}
__device__ __forceinline__ void mma_f16(float& d0, float& d1, float& d2, float& d3,
                                        u32 a0, u32 a1, u32 a2, u32 a3, u32 b0, u32 b1) {
    asm volatile("mma.sync.aligned.m16n8k16.row.col.f32.f16.f16.f32 "
                 "{%0,%1,%2,%3},{%4,%5,%6,%7},{%8,%9},{%0,%1,%2,%3};"
                 : "+f"(d0), "+f"(d1), "+f"(d2), "+f"(d3)
                 : "r"(a0), "r"(a1), "r"(a2), "r"(a3), "r"(b0), "r"(b1));
}
__device__ __forceinline__ void sts128(u32 a, u32 x, u32 y, u32 z, u32 w) {
    asm volatile("st.shared.v4.b32 [%0],{%1,%2,%3,%4};" :: "r"(a), "r"(x), "r"(y), "r"(z), "r"(w) : "memory");
}
__device__ __forceinline__ u32 f16x2(float lo, float hi) {   // lo -> low half
    u32 r; asm("cvt.rn.f16x2.f32 %0, %1, %2;" : "=r"(r) : "f"(hi), "f"(lo));
    return r;
}
__device__ __forceinline__ u32 hmul2(u32 a, u32 b) {
    u32 r; asm("mul.f16x2 %0,%1,%2;" : "=r"(r) : "r"(a), "r"(b)); return r;
}
__device__ __forceinline__ u32 hfma2(u32 a, u32 b, u32 c) {
    u32 r; asm("fma.rn.f16x2 %0,%1,%2,%3;" : "=r"(r) : "r"(a), "r"(b), "r"(c)); return r;
}

// ================= K1: transpose x -> fp16 channels-last image =================
__global__ __launch_bounds__(256) void k_transpose(const float* __restrict__ x) {
    __shared__ float tile[64][65];
    int b  = blockIdx.y;
    int p0 = blockIdx.x << 6;
    int t  = threadIdx.x;
    #pragma unroll
    for (int i = t; i < 4096; i += 256) {
        int c = i >> 6, p = i & 63;
        tile[c][p] = x[((size_t)(b * 64 + c)) * NPIX + p0 + p];
    }
    __syncthreads();
    #pragma unroll
    for (int i = t; i < 2048; i += 256) {
        int p = i >> 5, cp = i & 31;
        g_xh[((size_t)b * NPIX + p0 + p) * 32 + cp] =
            f16x2(tile[cp * 2][p], tile[cp * 2 + 1][p]);
    }
}

// ================= K0: weight prep (fp16 RN, pre-swizzled) =================
__global__ __launch_bounds__(256) void k_prep(const float* __restrict__ wker,
                                              const float* __restrict__ wof) {
    int i = blockIdx.x * 256 + threadIdx.x;
    if (i < 9 * 4096) {
        int n = i >> 12, r = i & 4095, oc = r >> 6, ch = r & 63;
        float v = wker[(oc * 64 + ch) * 9 + n];
        __half h = __float2half_rn(v);
        u32 sw = swz((u32)(oc * 128 + ch * 2)) >> 1;
        g_wf[n * 4096 + sw] = *(unsigned short*)&h;
    } else {
        int j = i - 9 * 4096;
        if (j < 9 * 2048) {
            int n = j >> 11, r = j & 2047, oc = r >> 6, ch = r & 63;
            float v = (oc < 18) ? wof[(oc * 64 + ch) * 9 + n] : 0.f;
            __half h = __float2half_rn(v);
            u32 sw = swz((u32)(oc * 128 + ch * 2)) >> 1;
            g_wof[n * 2048 + sw] = *(unsigned short*)&h;
        }
    }
}

// ================= K_MAIN =================
// smem: A ring 2 x 16K, B ring 2 x 8K, compact meta (4.5K + 9K) = 62976 B
#define AF(s)   ((s) * 16384)
#define BF(s)   (32768 + (s) * 8192)
#define OFF_MXY  49152
#define OFF_MLXY 53760
#define SMEM_MAIN 62976

// phase-0 A build: pure fp16 copy from g_xh (4 LDG.128 + 4 STS.128)
__device__ __forceinline__ void build_a0(const u32* __restrict__ xh,
                                         int hh, int ww, int tap,
                                         int lp, int q, u32 aF) {
    int sh_ = hh + tap / 3 - 1, sw_ = ww + tap % 3 - 1;
    bool ok = ((unsigned)sh_ < 96u) & ((unsigned)sw_ < 96u);
    uint4 v[4];
    if (ok) {
        const uint4* src = (const uint4*)(xh + (size_t)(sh_ * 96 + sw_) * 32) + q * 4;
        #pragma unroll
        for (int j = 0; j < 4; j++) v[j] = src[j];
    } else {
        #pragma unroll
        for (int j = 0; j < 4; j++) v[j] = make_uint4(0, 0, 0, 0);
    }
    u32 rowb = (u32)(lp * 128 + q * 64);
    #pragma unroll
    for (int j = 0; j < 4; j++) {
        u32 sa = swz(rowb + j * 16);
        sts128(aF + sa, v[j].x, v[j].y, v[j].z, v[j].w);
    }
}

// phase-1 sampler: fp16 gather + packed HFMA2 blend; lane owns 8 contiguous ch
__device__ __forceinline__ void sample_pix(const u32* __restrict__ xh,
                                           const int* __restrict__ mxy,
                                           const float2* __restrict__ mlxy,
                                           int lp, int n, int l8, u32 aF) {
    int mi = lp * 9 + n;
    int xy = mxy[mi];
    float2 l = mlxy[mi];
    int x0 = xy >> 16, y0 = (xy << 16) >> 16;
    int x1 = x0 + 1, y1 = y0 + 1;
    float lx = l.x, ly = l.y;
    float w00 = (1.f - lx) * (1.f - ly);
    float w10 = lx * (1.f - ly);
    float w01 = (1.f - lx) * ly;
    float w11 = lx * ly;
    if ((unsigned)x0 >= 96u) { w00 = 0.f; w01 = 0.f; }
    if ((unsigned)x1 >= 96u) { w10 = 0.f; w11 = 0.f; }
    if ((unsigned)y0 >= 96u) { w00 = 0.f; w10 = 0.f; }
    if ((unsigned)y1 >= 96u) { w01 = 0.f; w11 = 0.f; }
    int cx0 = min(max(x0, 0), 95), cx1 = min(max(x1, 0), 95);
    int cy0 = min(max(y0, 0), 95), cy1 = min(max(y1, 0), 95);
    const uint4* pA = (const uint4*)(xh + (size_t)(cx0 * 96 + cy0) * 32) + l8;
    const uint4* pB = (const uint4*)(xh + (size_t)(cx1 * 96 + cy0) * 32) + l8;
    const uint4* pC = (const uint4*)(xh + (size_t)(cx0 * 96 + cy1) * 32) + l8;
    const uint4* pD = (const uint4*)(xh + (size_t)(cx1 * 96 + cy1) * 32) + l8;
    uint4 A = *pA, B = *pB, C = *pC, D = *pD;
    u32 W00 = f16x2(w00, w00), W10 = f16x2(w10, w10);
    u32 W01 = f16x2(w01, w01), W11 = f16x2(w11, w11);
    u32 r0 = hmul2(A.x, W00), r1 = hmul2(A.y, W00);
    u32 r2 = hmul2(A.z, W00), r3 = hmul2(A.w, W00);
    r0 = hfma2(B.x, W10, r0); r1 = hfma2(B.y, W10, r1);
    r2 = hfma2(B.z, W10, r2); r3 = hfma2(B.w, W10, r3);
    r0 = hfma2(C.x, W01, r0); r1 = hfma2(C.y, W01, r1);
    r2 = hfma2(C.z, W01, r2); r3 = hfma2(C.w, W01, r3);
    r0 = hfma2(D.x, W11, r0); r1 = hfma2(D.y, W11, r1);
    r2 = hfma2(D.z, W11, r2); r3 = hfma2(D.w, W11, r3);
    u32 sa = swz((u32)(lp * 128 + l8 * 16));
    sts128(aF + sa, r0, r1, r2, r3);
}

__global__ __launch_bounds__(256, 2) void k_main(const float* __restrict__ bof,
                                                 const float* __restrict__ bker,
                                                 float* __restrict__ out) {
    extern __shared__ char smc[];
    u32 sb = s2u(smc);
    int t = threadIdx.x, wid = t >> 5, ln = t & 31;
    int b = blockIdx.y;
    int p0 = blockIdx.x * 128;
    const u32* xh = g_xh + (size_t)b * NPIX * 32;

    // ========== PHASE 0: offset conv (fp16 single-term), double-buffered ==========
    float acc0[3][4];
    #pragma unroll
    for (int nt = 0; nt < 3; nt++)
        #pragma unroll
        for (int j = 0; j < 4; j++) acc0[nt][j] = 0.f;

    {
        int lp = t >> 1, q = t & 1;
        int pix = p0 + lp, hh = pix / 96, ww = pix - hh * 96;
        u32 arow = (u32)((wid * 16 + (ln & 15)) * 128 + ((ln >> 4) * 16));
        u32 brow = (u32)(((((ln >> 4) << 3) + (ln & 7))) * 128 + (((ln >> 3) & 1) * 16));

        // prologue: build A(0), stage B(0)
        ((uint4*)(smc + BF(0)))[t] = ((const uint4*)g_wof)[t];
        build_a0(xh, hh, ww, 0, lp, q, sb + AF(0));
        __syncthreads();

        for (int tap = 0; tap < 9; tap++) {
            int s = tap & 1;
            if (tap < 8) {
                ((uint4*)(smc + BF(1 - s)))[t] = ((const uint4*)g_wof)[(tap + 1) * 256 + t];
                build_a0(xh, hh, ww, tap + 1, lp, q, sb + AF(1 - s));
            }
            {
                u32 aF = sb + AF(s), bF = sb + BF(s);
                #pragma unroll
                for (int k = 0; k < 4; k++) {
                    u32 ka = (u32)(k * 32);
                    u32 ah[4], bh[8];
                    ldsm4(aF + swz(arow + ka), ah[0], ah[1], ah[2], ah[3]);
                    ldsm4(bF + swz(brow + ka), bh[0], bh[1], bh[2], bh[3]);
                    ldsm4(bF + swz(brow + 2048 + ka), bh[4], bh[5], bh[6], bh[7]);
                    #pragma unroll
                    for (int nt = 0; nt < 3; nt++)
                        mma_f16(acc0[nt][0], acc0[nt][1], acc0[nt][2], acc0[nt][3],
                                ah[0], ah[1], ah[2], ah[3], bh[nt*2], bh[nt*2+1]);
                }
            }
            __syncthreads();
        }
    }
    // stage offset outputs as f32 (reuse A region)
    {
        float* dst = (float*)(smc + AF(0));
        int pr = wid * 16 + (ln >> 2);
        int pc = (ln & 3) * 2;
        #pragma unroll
        for (int nt = 0; nt < 3; nt++) {
            dst[pr * 24 + nt * 8 + pc]           = acc0[nt][0];
            dst[pr * 24 + nt * 8 + pc + 1]       = acc0[nt][1];
            dst[(pr + 8) * 24 + nt * 8 + pc]     = acc0[nt][2];
            dst[(pr + 8) * 24 + nt * 8 + pc + 1] = acc0[nt][3];
        }
    }
    __syncthreads();
    // bilinear meta (compact: packed int corner + float2 fractions)
    {
        const float* dsm = (const float*)(smc + AF(0));
        int*    mxy  = (int*)(smc + OFF_MXY);
        float2* mlxy = (float2*)(smc + OFF_MLXY);
        for (int i = t; i < 1152; i += 256) {
            int lp = i / 9, n = i - lp * 9;
            int pix = p0 + lp, hh = pix / 96, ww = pix - hh * 96;
            float ox = dsm[lp * 24 + n]     + __ldg(bof + n);
            float oy = dsm[lp * 24 + 9 + n] + __ldg(bof + 9 + n);
            float px = (float)(hh + n / 3 - 1) + ox;
            float py = (float)(ww + n % 3 - 1) + oy;
            px = fminf(fmaxf(px, -10000.f), 10000.f);
            py = fminf(fmaxf(py, -10000.f), 10000.f);
            float fx = floorf(px), fy = floorf(py);
            int x0 = (int)fx, y0 = (int)fy;
            mxy[i]  = (x0 << 16) | (y0 & 0xffff);
            mlxy[i] = make_float2(px - fx, py - fy);
        }
    }
    __syncthreads();

    // ========== PHASE 1: sampled main conv, double-buffered ==========
    const int*    mxy  = (const int*)(smc + OFF_MXY);
    const float2* mlxy = (const float2*)(smc + OFF_MLXY);
    int l8 = ln & 7, g4 = ln >> 3;

    float acc[2][4][4];
    #pragma unroll
    for (int mt = 0; mt < 2; mt++)
        #pragma unroll
        for (int nt = 0; nt < 4; nt++)
            #pragma unroll
            for (int j = 0; j < 4; j++) acc[mt][nt][j] = 0.f;

    int mbase = (wid & 3) * 32, nbase = (wid >> 2) * 32;
    u32 arow = (u32)((mbase + (ln & 15)) * 128 + ((ln >> 4) * 16));
    u32 brow = (u32)((nbase + ((ln >> 4) << 3) + (ln & 7)) * 128 + (((ln >> 3) & 1) * 16));

    // prologue: stage B(0) + sample(0) into stage 0
    {
        const uint4* sw4 = (const uint4*)g_wf;
        ((uint4*)(smc + BF(0)))[t]       = sw4[t];
        ((uint4*)(smc + BF(0)))[t + 256] = sw4[t + 256];
        #pragma unroll
        for (int i = 0; i < 4; i++) {
            int lp = wid * 16 + i * 4 + g4;
            sample_pix(xh, mxy, mlxy, lp, 0, l8, sb + AF(0));
        }
    }
    __syncthreads();

    for (int n = 0; n < 9; n++) {
        int s = n & 1;
        if (n < 8) {
            const uint4* sw4 = (const uint4*)g_wf + (n + 1) * 512;
            ((uint4*)(smc + BF(1 - s)))[t]       = sw4[t];
            ((uint4*)(smc + BF(1 - s)))[t + 256] = sw4[t + 256];
            #pragma unroll
            for (int i = 0; i < 4; i++) {
                int lp = wid * 16 + i * 4 + g4;
                sample_pix(xh, mxy, mlxy, lp, n + 1, l8, sb + AF(1 - s));
            }
        }
        {
            u32 aF = sb + AF(s), bF = sb + BF(s);
            #pragma unroll
            for (int k = 0; k < 4; k++) {
                u32 ka = (u32)(k * 32);
                u32 ah[8], bh[8];
                ldsm4(aF + swz(arow + ka),        ah[0], ah[1], ah[2], ah[3]);
                ldsm4(aF + swz(arow + 2048 + ka), ah[4], ah[5], ah[6], ah[7]);
                ldsm4(bF + swz(brow + ka),        bh[0], bh[1], bh[2], bh[3]);
                ldsm4(bF + swz(brow + 2048 + ka), bh[4], bh[5], bh[6], bh[7]);
                #pragma unroll
                for (int mt = 0; mt < 2; mt++) {
                    #pragma unroll
                    for (int nt = 0; nt < 4; nt++) {
                        mma_f16(acc[mt][nt][0], acc[mt][nt][1], acc[mt][nt][2], acc[mt][nt][3],
                                ah[mt*4], ah[mt*4+1], ah[mt*4+2], ah[mt*4+3], bh[nt*2], bh[nt*2+1]);
                    }
                }
            }
        }
        __syncthreads();
    }

    // ================= epilogue =================
    {
        #pragma unroll
        for (int mt = 0; mt < 2; mt++) {
            #pragma unroll
            for (int nt = 0; nt < 4; nt++) {
                int pix = p0 + mbase + mt * 16 + (ln >> 2);
                int oc  = nbase + nt * 8 + (ln & 3) * 2;
                float b0 = __ldg(bker + oc), b1 = __ldg(bker + oc + 1);
                size_t base = ((size_t)(b * 64 + oc)) * NPIX + pix;
                out[base]            = acc[mt][nt][0] + b0;
                out[base + NPIX]     = acc[mt][nt][1] + b1;
                out[base + 8]        = acc[mt][nt][2] + b0;
                out[base + NPIX + 8] = acc[mt][nt][3] + b1;
            }
        }
    }
}

// ================= launch =================
extern "C" void kernel_launch(void* const* d_in, const int* in_sizes, int n_in,
                              void* d_out, int out_size) {
    const float* x     = (const float*)d_in[0];
    const float* w_off = (const float*)d_in[1];
    const float* b_off = (const float*)d_in[2];
    const float* w_ker = (const float*)d_in[3];
    const float* b_ker = (const float*)d_in[4];
    float* out = (float*)d_out;

    cudaFuncSetAttribute(k_main, cudaFuncAttributeMaxDynamicSharedMemorySize, SMEM_MAIN);

    k_transpose<<<dim3(NPIX / 64, BB), 256>>>(x);
    k_prep<<<(9 * 4096 + 9 * 2048 + 255) / 256, 256>>>(w_ker, w_off);
    k_main<<<dim3(NPIX / 128, BB), 256, SMEM_MAIN>>>(b_off, b_ker, out);
}